// round 1
// baseline (speedup 1.0000x reference)
#include <cuda_runtime.h>
#include <cstdint>
#include <cstddef>

// Problem constants
#define BB 4
#define HH 128
#define WW 128
#define DD 64
#define NP 9
#define PTOT (BB*HH*WW)        // 65536 pixels

// ---------------------------------------------------------------------------
// Scratch (static device arrays; no allocation allowed)
// ---------------------------------------------------------------------------
__device__ float g_xK[(size_t)PTOT * 576];   // [P, 9*64]
__device__ float g_xV[(size_t)PTOT * 576];   // [P, 9*64]
__device__ float g_xQ[(size_t)PTOT * 64];    // [P, 64]
__device__ float g_attn[(size_t)PTOT * 64];  // [P, 64]
__device__ float g_t1[(size_t)PTOT * 64];    // [P, 64]
__device__ float g_t2[(size_t)PTOT * 128];   // [P, 128]

// ---------------------------------------------------------------------------
// Generic GEMM: C[M,N] = A[M,64] @ W[64,N] (+bias, relu). Tile 64x64, K=64.
// grid = (M/64, N/64), block = 256
// ---------------------------------------------------------------------------
__global__ __launch_bounds__(256) void gemm_k64(
    const float* __restrict__ A, const float* __restrict__ W,
    const float* __restrict__ bias, float* __restrict__ C,
    int N, int do_relu)
{
    __shared__ float Ast[64 * 65];  // transposed: Ast[k][m]
    __shared__ float Ws [64 * 65];  // Ws[k][n]

    const int m0 = blockIdx.x * 64;
    const int n0 = blockIdx.y * 64;
    const int tid = threadIdx.x;

    // Cooperative loads (coalesced on global)
    #pragma unroll
    for (int idx = tid; idx < 4096; idx += 256) {
        int r = idx >> 6, c = idx & 63;
        Ast[c * 65 + r] = A[(size_t)(m0 + r) * 64 + c];
        Ws [r * 65 + c] = W[(size_t)r * N + n0 + c];
    }
    __syncthreads();

    const int tx = tid & 15;   // n-tile
    const int ty = tid >> 4;   // m-tile
    float acc[4][4] = {};

    #pragma unroll 8
    for (int k = 0; k < 64; k++) {
        float a[4], b[4];
        #pragma unroll
        for (int i = 0; i < 4; i++) a[i] = Ast[k * 65 + ty * 4 + i];
        #pragma unroll
        for (int j = 0; j < 4; j++) b[j] = Ws[k * 65 + tx * 4 + j];
        #pragma unroll
        for (int i = 0; i < 4; i++)
            #pragma unroll
            for (int j = 0; j < 4; j++)
                acc[i][j] = fmaf(a[i], b[j], acc[i][j]);
    }

    #pragma unroll
    for (int i = 0; i < 4; i++) {
        int m = m0 + ty * 4 + i;
        #pragma unroll
        for (int j = 0; j < 4; j++) {
            int n = n0 + tx * 4 + j;
            float v = acc[i][j];
            if (bias) v += bias[n];
            if (do_relu) v = fmaxf(v, 0.0f);
            C[(size_t)m * N + n] = v;
        }
    }
}

// ---------------------------------------------------------------------------
// Attention: one warp per pixel, 2 channels per lane, 16-lane head groups.
// Padded taps: k contributes 0 to score (matches masked-multiply, not -inf),
// v contributes 0 to the weighted sum.
// grid = PTOT/8, block = 256
// ---------------------------------------------------------------------------
__global__ __launch_bounds__(256) void attn_kernel(
    const float* __restrict__ xK, const float* __restrict__ xV,
    const float* __restrict__ xQ, float* __restrict__ out)
{
    const int warp = threadIdx.x >> 5;
    const int lane = threadIdx.x & 31;
    const int p = blockIdx.x * 8 + warp;

    const int hw = p & (HH * WW - 1);
    const int h = hw >> 7;
    const int w = hw & 127;
    const int c0 = lane * 2;

    const float2 q = *(const float2*)(xQ + (size_t)p * 64 + c0);

    float s[NP];
    #pragma unroll
    for (int t = 0; t < NP; t++) {
        const int di = t / 3 - 1, dj = t % 3 - 1;
        const bool valid = (unsigned)(h + di) < HH && (unsigned)(w + dj) < WW;
        float2 k = make_float2(0.0f, 0.0f);
        if (valid) {
            const int pp = p + di * WW + dj;
            k = *(const float2*)(xK + (size_t)pp * 576 + t * 64 + c0);
        }
        float part = k.x * q.x + k.y * q.y;
        // reduce over the 16-lane head group (32 channels)
        #pragma unroll
        for (int off = 8; off >= 1; off >>= 1)
            part += __shfl_xor_sync(0xffffffffu, part, off);
        s[t] = part * (1.0f / 3.0f);
    }

    // softmax over taps
    float m = s[0];
    #pragma unroll
    for (int t = 1; t < NP; t++) m = fmaxf(m, s[t]);
    float e[NP], sum = 0.0f;
    #pragma unroll
    for (int t = 0; t < NP; t++) { e[t] = expf(s[t] - m); sum += e[t]; }
    const float inv = 1.0f / sum;

    float2 acc = make_float2(0.0f, 0.0f);
    #pragma unroll
    for (int t = 0; t < NP; t++) {
        const int di = t / 3 - 1, dj = t % 3 - 1;
        const bool valid = (unsigned)(h + di) < HH && (unsigned)(w + dj) < WW;
        if (valid) {
            const int pp = p + di * WW + dj;
            const float2 v = *(const float2*)(xV + (size_t)pp * 576 + t * 64 + c0);
            const float al = e[t] * inv;
            acc.x = fmaf(al, v.x, acc.x);
            acc.y = fmaf(al, v.y, acc.y);
        }
    }
    *(float2*)(out + (size_t)p * 64 + c0) = acc;
}

// ---------------------------------------------------------------------------
// 3x3 SAME conv, implicit GEMM. 8x8 pixel tile, 10x10 halo (channel-chunked
// by 64), per-tap 64x64 weight chunk in smem, 4px x 4ch regs per thread.
// Weight layout: [3][3][CIN][COUT] row-major. bias + relu fused.
// grid = (W/8, H/8, B * COUT/64), block = 256
// ---------------------------------------------------------------------------
template <int CIN, int COUT>
__global__ __launch_bounds__(256) void conv3x3_kernel(
    const float* __restrict__ in, const float* __restrict__ wgt,
    const float* __restrict__ bias, float* __restrict__ out)
{
    __shared__ float halo[64 * 101];  // [c][y*10+x], stride 101 avoids conflicts
    __shared__ float wtap[64 * 64];   // [cin_local][cout_local]

    constexpr int ZDIV = COUT / 64;
    const int bx = blockIdx.x, by = blockIdx.y;
    const int co0 = (blockIdx.z % ZDIV) * 64;
    const int b   = blockIdx.z / ZDIV;
    const int tid = threadIdx.x;

    const int cg = tid & 15;          // cout sub: channels cg*4 .. cg*4+3
    const int pg = tid >> 4;          // pixel group
    const int prow = pg >> 1;         // tile row 0..7
    const int pxb = (pg & 1) * 4;     // tile col base 0 or 4

    const int y0 = by * 8, x0 = bx * 8;

    float acc[4][4] = {};             // [pixel][cout]

    for (int cin0 = 0; cin0 < CIN; cin0 += 64) {
        __syncthreads();  // previous halo consumers done
        // load halo chunk (zero padded)
        for (int idx = tid; idx < 6400; idx += 256) {
            int c = idx & 63;
            int sp = idx >> 6;
            int hy = sp / 10, hx = sp - hy * 10;
            int gy = y0 + hy - 1, gx = x0 + hx - 1;
            float v = 0.0f;
            if ((unsigned)gy < HH && (unsigned)gx < WW)
                v = in[(((size_t)b * HH + gy) * WW + gx) * CIN + cin0 + c];
            halo[c * 101 + hy * 10 + hx] = v;
        }

        for (int t = 0; t < 9; t++) {
            __syncthreads();  // halo ready / previous wtap consumers done
            for (int idx = tid; idx < 4096; idx += 256) {
                int d = idx >> 6, c = idx & 63;
                wtap[d * 64 + c] = wgt[((size_t)t * CIN + cin0 + d) * COUT + co0 + c];
            }
            __syncthreads();

            const int ti = t / 3, tj = t % 3;
            const int base = (prow + ti) * 10 + pxb + tj;
            #pragma unroll 8
            for (int d = 0; d < 64; d++) {
                float a0 = halo[d * 101 + base + 0];
                float a1 = halo[d * 101 + base + 1];
                float a2 = halo[d * 101 + base + 2];
                float a3 = halo[d * 101 + base + 3];
                float4 wv = *(const float4*)&wtap[d * 64 + cg * 4];
                acc[0][0] = fmaf(a0, wv.x, acc[0][0]);
                acc[0][1] = fmaf(a0, wv.y, acc[0][1]);
                acc[0][2] = fmaf(a0, wv.z, acc[0][2]);
                acc[0][3] = fmaf(a0, wv.w, acc[0][3]);
                acc[1][0] = fmaf(a1, wv.x, acc[1][0]);
                acc[1][1] = fmaf(a1, wv.y, acc[1][1]);
                acc[1][2] = fmaf(a1, wv.z, acc[1][2]);
                acc[1][3] = fmaf(a1, wv.w, acc[1][3]);
                acc[2][0] = fmaf(a2, wv.x, acc[2][0]);
                acc[2][1] = fmaf(a2, wv.y, acc[2][1]);
                acc[2][2] = fmaf(a2, wv.z, acc[2][2]);
                acc[2][3] = fmaf(a2, wv.w, acc[2][3]);
                acc[3][0] = fmaf(a3, wv.x, acc[3][0]);
                acc[3][1] = fmaf(a3, wv.y, acc[3][1]);
                acc[3][2] = fmaf(a3, wv.z, acc[3][2]);
                acc[3][3] = fmaf(a3, wv.w, acc[3][3]);
            }
        }
    }

    const int y = y0 + prow;
    #pragma unroll
    for (int px = 0; px < 4; px++) {
        const int x = x0 + pxb + px;
        const size_t o = (((size_t)b * HH + y) * WW + x) * COUT + co0 + cg * 4;
        #pragma unroll
        for (int c = 0; c < 4; c++) {
            float v = acc[px][c] + bias[co0 + cg * 4 + c];
            out[o + c] = fmaxf(v, 0.0f);
        }
    }
}

// ---------------------------------------------------------------------------
// Launch
// ---------------------------------------------------------------------------
extern "C" void kernel_launch(void* const* d_in, const int* in_sizes, int n_in,
                              void* d_out, int out_size)
{
    const float* x      = (const float*)d_in[0];
    const float* K_P    = (const float*)d_in[1];
    const float* V_P    = (const float*)d_in[2];
    const float* Q_P    = (const float*)d_in[3];
    const float* ff1_k  = (const float*)d_in[4];
    const float* ff1_b  = (const float*)d_in[5];
    const float* ff2_k  = (const float*)d_in[6];
    const float* ff2_b  = (const float*)d_in[7];
    const float* ff3_k  = (const float*)d_in[8];
    const float* ff3_b  = (const float*)d_in[9];
    float* out = (float*)d_out;

    float *xK, *xV, *xQ, *attn, *t1, *t2;
    cudaGetSymbolAddress((void**)&xK,   g_xK);
    cudaGetSymbolAddress((void**)&xV,   g_xV);
    cudaGetSymbolAddress((void**)&xQ,   g_xQ);
    cudaGetSymbolAddress((void**)&attn, g_attn);
    cudaGetSymbolAddress((void**)&t1,   g_t1);
    cudaGetSymbolAddress((void**)&t2,   g_t2);

    const dim3 blk(256);
    const int MT = PTOT / 64;  // 1024 m-tiles

    // Projections
    gemm_k64<<<dim3(MT, 9), blk>>>(x, K_P, nullptr, xK, 576, 0);
    gemm_k64<<<dim3(MT, 9), blk>>>(x, V_P, nullptr, xV, 576, 0);
    gemm_k64<<<dim3(MT, 1), blk>>>(x, Q_P, nullptr, xQ, 64, 0);

    // Attention (softmax over 9 taps, 2 heads)
    attn_kernel<<<PTOT / 8, blk>>>(xK, xV, xQ, attn);

    // FFN
    gemm_k64<<<dim3(MT, 1), blk>>>(attn, ff1_k, ff1_b, t1, 64, 1);
    conv3x3_kernel<64, 128><<<dim3(WW / 8, HH / 8, BB * 2), blk>>>(t1, ff2_k, ff2_b, t2);
    conv3x3_kernel<128, 64><<<dim3(WW / 8, HH / 8, BB), blk>>>(t2, ff3_k, ff3_b, out);
}

// round 2
// speedup vs baseline: 2.5519x; 2.5519x over previous
#include <cuda_runtime.h>
#include <cstdint>
#include <cstddef>

// Problem constants
#define BB 4
#define HH 128
#define WW 128
#define DD 64
#define NP 9
#define PTOT (BB*HH*WW)        // 65536 pixels

// ---------------------------------------------------------------------------
// Scratch (static device arrays; no allocation allowed)
// ---------------------------------------------------------------------------
__device__ float g_xK[(size_t)PTOT * 576];   // [P, 9*64]
__device__ float g_xV[(size_t)PTOT * 576];   // [P, 9*64]
__device__ float g_xQ[(size_t)PTOT * 64];    // [P, 64]
__device__ float g_attn[(size_t)PTOT * 64];  // [P, 64]
__device__ float g_t1[(size_t)PTOT * 64];    // [P, 64]
__device__ float g_t2[(size_t)PTOT * 128];   // [P, 128]

// ---------------------------------------------------------------------------
// tf32 helpers
// ---------------------------------------------------------------------------
__device__ __forceinline__ uint32_t tf32b(float x) {
    uint32_t u;
    asm("cvt.rna.tf32.f32 %0, %1;" : "=r"(u) : "f"(x));
    return u;
}

__device__ __forceinline__ void mma8(float* c, const uint32_t* a, const uint32_t* b) {
    asm volatile(
        "mma.sync.aligned.m16n8k8.row.col.f32.tf32.tf32.f32 "
        "{%0,%1,%2,%3}, {%4,%5,%6,%7}, {%8,%9}, {%0,%1,%2,%3};"
        : "+f"(c[0]), "+f"(c[1]), "+f"(c[2]), "+f"(c[3])
        : "r"(a[0]), "r"(a[1]), "r"(a[2]), "r"(a[3]),
          "r"(b[0]), "r"(b[1]));
}

// ---------------------------------------------------------------------------
// tf32 GEMM: C[M,N] = A[M,64] @ W[64,N] (+bias, relu)
// Block tile 128x64, K=64. 128 threads = 4 warps, warptile 32x64.
// A smem: [m][k] stride 68 (conflict-free A-frag LDS).
// W smem: fragment-shuffled order: section (kstep, nfrag) of 64 uints,
//         position lane*2 + reg -> uint2 LDS per fragment.
// grid = (M/128, N/64)
// ---------------------------------------------------------------------------
#define ASTRIDE 68

__global__ __launch_bounds__(128) void gemm_tf32(
    const float* __restrict__ A, const float* __restrict__ W,
    const float* __restrict__ bias, float* __restrict__ C,
    int N, int do_relu)
{
    extern __shared__ float smem[];
    float*    Ast = smem;                                   // 128*68 floats
    uint32_t* Bf  = (uint32_t*)(smem + 128 * ASTRIDE);      // 64*64 uints

    const int m0blk = blockIdx.x * 128;
    const int n0blk = blockIdx.y * 64;
    const int tid = threadIdx.x;

    // Load A (coalesced float4), convert to tf32
    #pragma unroll
    for (int idx = tid; idx < 128 * 16; idx += 128) {
        int r = idx >> 4, c4 = (idx & 15) * 4;
        float4 v = *(const float4*)(A + (size_t)(m0blk + r) * 64 + c4);
        float* dst = Ast + r * ASTRIDE + c4;
        dst[0] = __uint_as_float(tf32b(v.x));
        dst[1] = __uint_as_float(tf32b(v.y));
        dst[2] = __uint_as_float(tf32b(v.z));
        dst[3] = __uint_as_float(tf32b(v.w));
    }
    // Load W, shuffle into fragment order
    #pragma unroll
    for (int idx = tid; idx < 4096; idx += 128) {
        int k = idx >> 6, n = idx & 63;
        float w = W[(size_t)k * N + n0blk + n];
        int sec = (k >> 3) * 8 + (n >> 3);
        int ln  = ((n & 7) << 2) | (k & 3);
        int reg = (k & 7) >> 2;
        Bf[sec * 64 + ln * 2 + reg] = tf32b(w);
    }
    __syncthreads();

    const int warp = tid >> 5, lane = tid & 31;
    const int m0 = warp * 32;
    const int lr = lane >> 2, lc = lane & 3;

    float acc[2][8][4] = {};

    #pragma unroll
    for (int ks = 0; ks < 8; ks++) {
        uint32_t a[2][4];
        #pragma unroll
        for (int mf = 0; mf < 2; mf++) {
            const float* base = Ast + (m0 + mf * 16 + lr) * ASTRIDE + ks * 8 + lc;
            a[mf][0] = __float_as_uint(base[0]);
            a[mf][1] = __float_as_uint(base[8 * ASTRIDE]);
            a[mf][2] = __float_as_uint(base[4]);
            a[mf][3] = __float_as_uint(base[8 * ASTRIDE + 4]);
        }
        #pragma unroll
        for (int nf = 0; nf < 8; nf++) {
            uint2 b = *(const uint2*)&Bf[(ks * 8 + nf) * 64 + lane * 2];
            uint32_t br[2] = {b.x, b.y};
            mma8(acc[0][nf], a[0], br);
            mma8(acc[1][nf], a[1], br);
        }
    }

    // Epilogue
    #pragma unroll
    for (int mf = 0; mf < 2; mf++) {
        #pragma unroll
        for (int nf = 0; nf < 8; nf++) {
            int col = n0blk + nf * 8 + lc * 2;
            float bx_ = 0.f, by_ = 0.f;
            if (bias) { bx_ = bias[col]; by_ = bias[col + 1]; }
            int r0 = m0blk + m0 + mf * 16 + lr;
            float2 v0 = make_float2(acc[mf][nf][0] + bx_, acc[mf][nf][1] + by_);
            float2 v1 = make_float2(acc[mf][nf][2] + bx_, acc[mf][nf][3] + by_);
            if (do_relu) {
                v0.x = fmaxf(v0.x, 0.f); v0.y = fmaxf(v0.y, 0.f);
                v1.x = fmaxf(v1.x, 0.f); v1.y = fmaxf(v1.y, 0.f);
            }
            *(float2*)(C + (size_t)r0 * N + col) = v0;
            *(float2*)(C + (size_t)(r0 + 8) * N + col) = v1;
        }
    }
}

// ---------------------------------------------------------------------------
// Attention: unchanged fp32 (DRAM-bound). One warp per pixel.
// ---------------------------------------------------------------------------
__global__ __launch_bounds__(256) void attn_kernel(
    const float* __restrict__ xK, const float* __restrict__ xV,
    const float* __restrict__ xQ, float* __restrict__ out)
{
    const int warp = threadIdx.x >> 5;
    const int lane = threadIdx.x & 31;
    const int p = blockIdx.x * 8 + warp;

    const int hw = p & (HH * WW - 1);
    const int h = hw >> 7;
    const int w = hw & 127;
    const int c0 = lane * 2;

    const float2 q = *(const float2*)(xQ + (size_t)p * 64 + c0);

    float s[NP];
    #pragma unroll
    for (int t = 0; t < NP; t++) {
        const int di = t / 3 - 1, dj = t % 3 - 1;
        const bool valid = (unsigned)(h + di) < HH && (unsigned)(w + dj) < WW;
        float2 k = make_float2(0.0f, 0.0f);
        if (valid) {
            const int pp = p + di * WW + dj;
            k = *(const float2*)(xK + (size_t)pp * 576 + t * 64 + c0);
        }
        float part = k.x * q.x + k.y * q.y;
        #pragma unroll
        for (int off = 8; off >= 1; off >>= 1)
            part += __shfl_xor_sync(0xffffffffu, part, off);
        s[t] = part * (1.0f / 3.0f);
    }

    float m = s[0];
    #pragma unroll
    for (int t = 1; t < NP; t++) m = fmaxf(m, s[t]);
    float e[NP], sum = 0.0f;
    #pragma unroll
    for (int t = 0; t < NP; t++) { e[t] = expf(s[t] - m); sum += e[t]; }
    const float inv = 1.0f / sum;

    float2 acc = make_float2(0.0f, 0.0f);
    #pragma unroll
    for (int t = 0; t < NP; t++) {
        const int di = t / 3 - 1, dj = t % 3 - 1;
        const bool valid = (unsigned)(h + di) < HH && (unsigned)(w + dj) < WW;
        if (valid) {
            const int pp = p + di * WW + dj;
            const float2 v = *(const float2*)(xV + (size_t)pp * 576 + t * 64 + c0);
            const float al = e[t] * inv;
            acc.x = fmaf(al, v.x, acc.x);
            acc.y = fmaf(al, v.y, acc.y);
        }
    }
    *(float2*)(out + (size_t)p * 64 + c0) = acc;
}

// ---------------------------------------------------------------------------
// tf32 implicit-GEMM 3x3 SAME conv. Tile TH x 16 pixels, COUT channels.
// 256 threads = 8 warps, warptile 32x64 pixels-by-couts.
// halo smem: [(TH+2)*18][68-padded channels] per 64-chunk of CIN.
// weight smem: per-tap 64 x COUT in fragment order.
// grid = (W/16, H/TH, B)
// ---------------------------------------------------------------------------
template <int CIN, int COUT, int TH>
__global__ __launch_bounds__(256) void conv_tf32(
    const float* __restrict__ in, const float* __restrict__ wgt,
    const float* __restrict__ bias, float* __restrict__ out)
{
    constexpr int TW = 16;
    constexpr int HW2 = TW + 2;
    constexpr int PSTRIDE = 68;
    constexpr int HALO_F = (TH + 2) * HW2 * PSTRIDE;
    constexpr int NWN = COUT / 64;      // n-warps per block
    constexpr int CHUNKS = CIN / 64;

    extern __shared__ float smem[];
    float*    halo = smem;                       // HALO_F floats
    uint32_t* Bf   = (uint32_t*)(smem + HALO_F); // 64*COUT uints

    const int x0 = blockIdx.x * TW;
    const int y0 = blockIdx.y * TH;
    const int b  = blockIdx.z;
    const int tid = threadIdx.x;
    const int warp = tid >> 5, lane = tid & 31;
    const int wm = warp / NWN, wn = warp % NWN;
    const int lr = lane >> 2, lc = lane & 3;

    float acc[2][8][4] = {};

    // pixel rows handled by this thread's A fragments: m = wm*32 + mf*16 + r8*8 + lr
    int pixoff[2][2];
    #pragma unroll
    for (int mf = 0; mf < 2; mf++)
        #pragma unroll
        for (int r8 = 0; r8 < 2; r8++) {
            int m = wm * 32 + mf * 16 + r8 * 8 + lr;
            int py = m >> 4, px = m & 15;
            pixoff[mf][r8] = (py * HW2 + px) * PSTRIDE;
        }

    for (int ch = 0; ch < CHUNKS; ch++) {
        const int cin0 = ch * 64;
        __syncthreads();
        // halo chunk load (float4 over channels), tf32 convert, zero-pad edges
        for (int idx = tid * 4; idx < (TH + 2) * HW2 * 64; idx += 256 * 4) {
            int c = idx & 63;
            int sp = idx >> 6;
            int hy = sp / HW2, hx = sp - hy * HW2;
            int gy = y0 + hy - 1, gx = x0 + hx - 1;
            float4 v = make_float4(0.f, 0.f, 0.f, 0.f);
            if ((unsigned)gy < HH && (unsigned)gx < WW)
                v = *(const float4*)(in + (((size_t)b * HH + gy) * WW + gx) * CIN + cin0 + c);
            float* dst = halo + sp * PSTRIDE + c;
            dst[0] = __uint_as_float(tf32b(v.x));
            dst[1] = __uint_as_float(tf32b(v.y));
            dst[2] = __uint_as_float(tf32b(v.z));
            dst[3] = __uint_as_float(tf32b(v.w));
        }

        for (int t = 0; t < 9; t++) {
            __syncthreads();   // halo ready / previous tap's Bf consumed
            // weight chunk -> fragment order
            for (int idx = tid; idx < 64 * COUT; idx += 256) {
                int k = idx / COUT, n = idx % COUT;
                float w = wgt[((size_t)t * CIN + cin0 + k) * COUT + n];
                int sec = (k >> 3) * (COUT / 8) + (n >> 3);
                int ln  = ((n & 7) << 2) | (k & 3);
                int reg = (k & 7) >> 2;
                Bf[sec * 64 + ln * 2 + reg] = tf32b(w);
            }
            __syncthreads();

            const int ti = t / 3, tj = t % 3;
            const int toff = (ti * HW2 + tj) * PSTRIDE;

            #pragma unroll
            for (int ks = 0; ks < 8; ks++) {
                uint32_t a[2][4];
                #pragma unroll
                for (int mf = 0; mf < 2; mf++) {
                    const float* b0 = halo + pixoff[mf][0] + toff + ks * 8 + lc;
                    const float* b1 = halo + pixoff[mf][1] + toff + ks * 8 + lc;
                    a[mf][0] = __float_as_uint(b0[0]);
                    a[mf][1] = __float_as_uint(b1[0]);
                    a[mf][2] = __float_as_uint(b0[4]);
                    a[mf][3] = __float_as_uint(b1[4]);
                }
                #pragma unroll
                for (int nf = 0; nf < 8; nf++) {
                    int sec = ks * (COUT / 8) + wn * 8 + nf;
                    uint2 bv = *(const uint2*)&Bf[sec * 64 + lane * 2];
                    uint32_t br[2] = {bv.x, bv.y};
                    mma8(acc[0][nf], a[0], br);
                    mma8(acc[1][nf], a[1], br);
                }
            }
        }
    }

    // Epilogue: bias + relu, float2 stores
    #pragma unroll
    for (int mf = 0; mf < 2; mf++) {
        #pragma unroll
        for (int r8 = 0; r8 < 2; r8++) {
            int m = wm * 32 + mf * 16 + r8 * 8 + lr;
            int py = m >> 4, px = m & 15;
            int y = y0 + py, x = x0 + px;
            size_t base = (((size_t)b * HH + y) * WW + x) * COUT;
            #pragma unroll
            for (int nf = 0; nf < 8; nf++) {
                int n = wn * 64 + nf * 8 + lc * 2;
                float2 v;
                v.x = acc[mf][nf][r8 * 2 + 0] + bias[n];
                v.y = acc[mf][nf][r8 * 2 + 1] + bias[n + 1];
                v.x = fmaxf(v.x, 0.f);
                v.y = fmaxf(v.y, 0.f);
                *(float2*)(out + base + n) = v;
            }
        }
    }
}

// ---------------------------------------------------------------------------
// Launch
// ---------------------------------------------------------------------------
extern "C" void kernel_launch(void* const* d_in, const int* in_sizes, int n_in,
                              void* d_out, int out_size)
{
    const float* x      = (const float*)d_in[0];
    const float* K_P    = (const float*)d_in[1];
    const float* V_P    = (const float*)d_in[2];
    const float* Q_P    = (const float*)d_in[3];
    const float* ff1_k  = (const float*)d_in[4];
    const float* ff1_b  = (const float*)d_in[5];
    const float* ff2_k  = (const float*)d_in[6];
    const float* ff2_b  = (const float*)d_in[7];
    const float* ff3_k  = (const float*)d_in[8];
    const float* ff3_b  = (const float*)d_in[9];
    float* out = (float*)d_out;

    float *xK, *xV, *xQ, *attn, *t1, *t2;
    cudaGetSymbolAddress((void**)&xK,   g_xK);
    cudaGetSymbolAddress((void**)&xV,   g_xV);
    cudaGetSymbolAddress((void**)&xQ,   g_xQ);
    cudaGetSymbolAddress((void**)&attn, g_attn);
    cudaGetSymbolAddress((void**)&t1,   g_t1);
    cudaGetSymbolAddress((void**)&t2,   g_t2);

    const int GEMM_SMEM  = 128 * ASTRIDE * 4 + 64 * 64 * 4;            // 51200
    const int CONV2_SMEM = 10 * 18 * 68 * 4 + 64 * 128 * 4;            // 81728
    const int CONV3_SMEM = 18 * 18 * 68 * 4 + 64 * 64 * 4;             // 104512

    cudaFuncSetAttribute(gemm_tf32, cudaFuncAttributeMaxDynamicSharedMemorySize, GEMM_SMEM);
    cudaFuncSetAttribute(conv_tf32<64, 128, 8>,  cudaFuncAttributeMaxDynamicSharedMemorySize, CONV2_SMEM);
    cudaFuncSetAttribute(conv_tf32<128, 64, 16>, cudaFuncAttributeMaxDynamicSharedMemorySize, CONV3_SMEM);

    const int MT = PTOT / 128;  // 512 m-tiles

    // Projections (tf32 tensor GEMMs)
    gemm_tf32<<<dim3(MT, 9), 128, GEMM_SMEM>>>(x, K_P, nullptr, xK, 576, 0);
    gemm_tf32<<<dim3(MT, 9), 128, GEMM_SMEM>>>(x, V_P, nullptr, xV, 576, 0);
    gemm_tf32<<<dim3(MT, 1), 128, GEMM_SMEM>>>(x, Q_P, nullptr, xQ, 64, 0);

    // Attention (fp32, memory-bound)
    attn_kernel<<<PTOT / 8, 256>>>(xK, xV, xQ, attn);

    // FFN
    gemm_tf32<<<dim3(MT, 1), 128, GEMM_SMEM>>>(attn, ff1_k, ff1_b, t1, 64, 1);
    conv_tf32<64, 128, 8><<<dim3(WW / 16, HH / 8, BB), 256, CONV2_SMEM>>>(t1, ff2_k, ff2_b, t2);
    conv_tf32<128, 64, 16><<<dim3(WW / 16, HH / 16, BB), 256, CONV3_SMEM>>>(t2, ff3_k, ff3_b, out);
}

// round 3
// speedup vs baseline: 3.8543x; 1.5103x over previous
#include <cuda_runtime.h>
#include <cuda_fp16.h>
#include <cstdint>
#include <cstddef>

#define BB 4
#define HH 128
#define WW 128
#define DD 64
#define NP 9
#define PTOT (BB*HH*WW)        // 65536 pixels
#define ASTRIDE 68

// ---------------------------------------------------------------------------
// Scratch
// ---------------------------------------------------------------------------
__device__ __half g_xKh[(size_t)PTOT * 576];
__device__ __half g_xVh[(size_t)PTOT * 576];
__device__ float  g_xr [(size_t)PTOT * 64];     // tf32-rounded x
__device__ float  g_xQ [(size_t)PTOT * 64];
__device__ float  g_attn[(size_t)PTOT * 64];    // tf32-rounded
__device__ float  g_t1 [(size_t)PTOT * 64];     // tf32-rounded
__device__ float  g_t2 [(size_t)PTOT * 128];    // tf32-rounded
// fragment-ordered tf32 weights
__device__ uint32_t g_wKf[9 * 4096];
__device__ uint32_t g_wVf[9 * 4096];
__device__ uint32_t g_wQf[4096];
__device__ uint32_t g_wF1f[4096];
__device__ uint32_t g_wc2f[9 * 8192];           // [tap][sec][64]
__device__ uint32_t g_wc3f[18 * 4096];          // [tap*2+chunk][sec][64]

// ---------------------------------------------------------------------------
// helpers
// ---------------------------------------------------------------------------
__device__ __forceinline__ uint32_t tf32b(float x) {
    uint32_t u;
    asm("cvt.rna.tf32.f32 %0, %1;" : "=r"(u) : "f"(x));
    return u;
}
__device__ __forceinline__ float tf32r(float x) { return __uint_as_float(tf32b(x)); }

__device__ __forceinline__ void mma8(float* c, const uint32_t* a, const uint32_t* b) {
    asm volatile(
        "mma.sync.aligned.m16n8k8.row.col.f32.tf32.tf32.f32 "
        "{%0,%1,%2,%3}, {%4,%5,%6,%7}, {%8,%9}, {%0,%1,%2,%3};"
        : "+f"(c[0]), "+f"(c[1]), "+f"(c[2]), "+f"(c[3])
        : "r"(a[0]), "r"(a[1]), "r"(a[2]), "r"(a[3]),
          "r"(b[0]), "r"(b[1]));
}

__device__ __forceinline__ void cp16(void* dst_smem, const void* src) {
    uint32_t d = (uint32_t)__cvta_generic_to_shared(dst_smem);
    asm volatile("cp.async.cg.shared.global [%0], [%1], 16;" :: "r"(d), "l"(src) : "memory");
}
__device__ __forceinline__ void cp_commit() { asm volatile("cp.async.commit_group;" ::: "memory"); }
__device__ __forceinline__ void cp_wait0()  { asm volatile("cp.async.wait_group 0;"  ::: "memory"); }

// ---------------------------------------------------------------------------
// Prep: round x to tf32
// ---------------------------------------------------------------------------
__global__ __launch_bounds__(256) void prep_x(const float* __restrict__ x, float* __restrict__ xr)
{
    size_t i = ((size_t)blockIdx.x * 256 + threadIdx.x) * 4;
    float4 v = *(const float4*)(x + i);
    v.x = tf32r(v.x); v.y = tf32r(v.y); v.z = tf32r(v.z); v.w = tf32r(v.w);
    *(float4*)(xr + i) = v;
}

// ---------------------------------------------------------------------------
// Prep: shuffle all weights into fragment order (tf32-rounded)
//   gemm frag idx (per 64-col tile): sec=(k>>3)*8+(nl>>3); ln=((nl&7)<<2)|(k&3);
//   reg=(k&7)>>2; pos = sec*64 + ln*2 + reg
// ---------------------------------------------------------------------------
__global__ __launch_bounds__(256) void prep_w(
    const float* __restrict__ K_P, const float* __restrict__ V_P,
    const float* __restrict__ Q_P, const float* __restrict__ F1,
    const float* __restrict__ W2, const float* __restrict__ W3)
{
    int i = blockIdx.x * 256 + threadIdx.x;
    if (i < 73728) {                               // K_P / V_P [64,576]
        const float* src = (i < 36864) ? K_P : V_P;
        uint32_t* dst = (i < 36864) ? g_wKf : g_wVf;
        int j = (i < 36864) ? i : i - 36864;
        int k = j / 576, n = j % 576;
        int nt = n >> 6, nl = n & 63;
        int pos = ((k >> 3) * 8 + (nl >> 3)) * 64 + (((nl & 7) << 2) | (k & 3)) * 2 + ((k & 7) >> 2);
        dst[nt * 4096 + pos] = tf32b(src[j]);
    } else if (i < 81920) {                        // Q_P / ff1 [64,64]
        int j = i - 73728;
        const float* src = (j < 4096) ? Q_P : F1;
        uint32_t* dst = (j < 4096) ? g_wQf : g_wF1f;
        int jj = j & 4095;
        int k = jj >> 6, n = jj & 63;
        int pos = ((k >> 3) * 8 + (n >> 3)) * 64 + (((n & 7) << 2) | (k & 3)) * 2 + ((k & 7) >> 2);
        dst[pos] = tf32b(src[jj]);
    } else if (i < 155648) {                       // ff2 [9][64][128]
        int j = i - 81920;
        int t = j >> 13, k = (j >> 7) & 63, n = j & 127;
        int pos = ((k >> 3) * 16 + (n >> 3)) * 64 + (((n & 7) << 2) | (k & 3)) * 2 + ((k & 7) >> 2);
        g_wc2f[t * 8192 + pos] = tf32b(W2[j]);
    } else {                                       // ff3 [9][128][64]
        int j = i - 155648;
        int t = j >> 13, k = (j >> 6) & 127, n = j & 63;
        int ch = k >> 6, kl = k & 63;
        int pos = ((kl >> 3) * 8 + (n >> 3)) * 64 + (((n & 7) << 2) | (kl & 3)) * 2 + ((kl & 7) >> 2);
        g_wc3f[(t * 2 + ch) * 4096 + pos] = tf32b(W3[j]);
    }
}

// ---------------------------------------------------------------------------
// K/V projection GEMM: A[128,64] x W[64,576] -> fp16 out.
// A fragments held in registers; 9 n-tiles looped with ping-pong cp.async B.
// grid (PTOT/128, 2): y=0 -> K, y=1 -> V. 128 threads.
// ---------------------------------------------------------------------------
__global__ __launch_bounds__(128) void gemm_kv(
    const float* __restrict__ xr,
    const uint32_t* __restrict__ wK, const uint32_t* __restrict__ wV,
    __half* __restrict__ outK, __half* __restrict__ outV)
{
    extern __shared__ char smraw[];
    float*    Ast = (float*)smraw;                          // 128*68
    uint32_t* Bf  = (uint32_t*)(smraw + 128 * ASTRIDE * 4); // 2 x 4096

    const uint32_t* wfrag = blockIdx.y ? wV : wK;
    __half* out           = blockIdx.y ? outV : outK;

    const int m0 = blockIdx.x * 128;
    const int tid = threadIdx.x;

    // stage A (raw copy; xr pre-rounded)
    #pragma unroll
    for (int i = 0; i < 16; i++) {
        int idx = tid + i * 128;
        int r = idx >> 4, c4 = (idx & 15) * 4;
        cp16(Ast + r * ASTRIDE + c4, xr + (size_t)(m0 + r) * 64 + c4);
    }
    // stage B tile 0
    #pragma unroll
    for (int i = 0; i < 8; i++) {
        int o = (tid + i * 128) * 4;
        cp16(Bf + o, wfrag + o);
    }
    cp_commit();
    cp_wait0();
    __syncthreads();

    const int warp = tid >> 5, lane = tid & 31;
    const int mw = warp * 32;
    const int lr = lane >> 2, lc = lane & 3;

    // hoist all A fragments to registers
    uint32_t a[8][2][4];
    #pragma unroll
    for (int ks = 0; ks < 8; ks++)
        #pragma unroll
        for (int mf = 0; mf < 2; mf++) {
            const float* base = Ast + (mw + mf * 16 + lr) * ASTRIDE + ks * 8 + lc;
            a[ks][mf][0] = __float_as_uint(base[0]);
            a[ks][mf][1] = __float_as_uint(base[8 * ASTRIDE]);
            a[ks][mf][2] = __float_as_uint(base[4]);
            a[ks][mf][3] = __float_as_uint(base[8 * ASTRIDE + 4]);
        }

    for (int nt = 0; nt < 9; nt++) {
        uint32_t* Bc = Bf + (nt & 1) * 4096;
        if (nt < 8) {
            uint32_t* Bn = Bf + ((nt + 1) & 1) * 4096;
            const uint32_t* src = wfrag + (nt + 1) * 4096;
            #pragma unroll
            for (int i = 0; i < 8; i++) {
                int o = (tid + i * 128) * 4;
                cp16(Bn + o, src + o);
            }
            cp_commit();
        }

        float acc[2][8][4] = {};
        #pragma unroll
        for (int ks = 0; ks < 8; ks++)
            #pragma unroll
            for (int nf = 0; nf < 8; nf++) {
                uint2 b = *(const uint2*)&Bc[(ks * 8 + nf) * 64 + lane * 2];
                uint32_t br[2] = {b.x, b.y};
                mma8(acc[0][nf], a[ks][0], br);
                mma8(acc[1][nf], a[ks][1], br);
            }

        // epilogue: fp16 store
        #pragma unroll
        for (int mf = 0; mf < 2; mf++) {
            int r0 = m0 + mw + mf * 16 + lr;
            #pragma unroll
            for (int nf = 0; nf < 8; nf++) {
                int col = nt * 64 + nf * 8 + lc * 2;
                *(__half2*)(out + (size_t)r0 * 576 + col) =
                    __floats2half2_rn(acc[mf][nf][0], acc[mf][nf][1]);
                *(__half2*)(out + (size_t)(r0 + 8) * 576 + col) =
                    __floats2half2_rn(acc[mf][nf][2], acc[mf][nf][3]);
            }
        }

        if (nt < 8) { cp_wait0(); __syncthreads(); }
    }
}

// ---------------------------------------------------------------------------
// Single-tile GEMM (Q projection / ff1): A[128,64] x W[64,64] -> fp32.
// MODE 0: plain store (Q). MODE 1: bias+relu+tf32-round (ff1).
// ---------------------------------------------------------------------------
template <int MODE>
__global__ __launch_bounds__(128) void gemm1(
    const float* __restrict__ A, const uint32_t* __restrict__ wfrag,
    const float* __restrict__ bias, float* __restrict__ C)
{
    extern __shared__ char smraw[];
    float*    Ast = (float*)smraw;
    uint32_t* Bf  = (uint32_t*)(smraw + 128 * ASTRIDE * 4);

    const int m0 = blockIdx.x * 128;
    const int tid = threadIdx.x;

    #pragma unroll
    for (int i = 0; i < 16; i++) {
        int idx = tid + i * 128;
        int r = idx >> 4, c4 = (idx & 15) * 4;
        cp16(Ast + r * ASTRIDE + c4, A + (size_t)(m0 + r) * 64 + c4);
    }
    #pragma unroll
    for (int i = 0; i < 8; i++) {
        int o = (tid + i * 128) * 4;
        cp16(Bf + o, wfrag + o);
    }
    cp_commit(); cp_wait0(); __syncthreads();

    const int warp = tid >> 5, lane = tid & 31;
    const int mw = warp * 32;
    const int lr = lane >> 2, lc = lane & 3;

    float acc[2][8][4] = {};
    #pragma unroll
    for (int ks = 0; ks < 8; ks++) {
        uint32_t a[2][4];
        #pragma unroll
        for (int mf = 0; mf < 2; mf++) {
            const float* base = Ast + (mw + mf * 16 + lr) * ASTRIDE + ks * 8 + lc;
            a[mf][0] = __float_as_uint(base[0]);
            a[mf][1] = __float_as_uint(base[8 * ASTRIDE]);
            a[mf][2] = __float_as_uint(base[4]);
            a[mf][3] = __float_as_uint(base[8 * ASTRIDE + 4]);
        }
        #pragma unroll
        for (int nf = 0; nf < 8; nf++) {
            uint2 b = *(const uint2*)&Bf[(ks * 8 + nf) * 64 + lane * 2];
            uint32_t br[2] = {b.x, b.y};
            mma8(acc[0][nf], a[0], br);
            mma8(acc[1][nf], a[1], br);
        }
    }

    #pragma unroll
    for (int mf = 0; mf < 2; mf++) {
        int r0 = m0 + mw + mf * 16 + lr;
        #pragma unroll
        for (int nf = 0; nf < 8; nf++) {
            int col = nf * 8 + lc * 2;
            float v[4] = {acc[mf][nf][0], acc[mf][nf][1], acc[mf][nf][2], acc[mf][nf][3]};
            if (MODE == 1) {
                float b0 = bias[col], b1 = bias[col + 1];
                v[0] = tf32r(fmaxf(v[0] + b0, 0.f));
                v[1] = tf32r(fmaxf(v[1] + b1, 0.f));
                v[2] = tf32r(fmaxf(v[2] + b0, 0.f));
                v[3] = tf32r(fmaxf(v[3] + b1, 0.f));
            }
            *(float2*)(C + (size_t)r0 * 64 + col)       = make_float2(v[0], v[1]);
            *(float2*)(C + (size_t)(r0 + 8) * 64 + col) = make_float2(v[2], v[3]);
        }
    }
}

// ---------------------------------------------------------------------------
// Attention (fp16 K/V, fp32 Q). Output tf32-rounded. One warp / pixel.
// ---------------------------------------------------------------------------
__global__ __launch_bounds__(256) void attn_kernel(
    const __half* __restrict__ xK, const __half* __restrict__ xV,
    const float* __restrict__ xQ, float* __restrict__ out)
{
    const int warp = threadIdx.x >> 5;
    const int lane = threadIdx.x & 31;
    const int p = blockIdx.x * 8 + warp;

    const int hw = p & (HH * WW - 1);
    const int h = hw >> 7;
    const int w = hw & 127;
    const int c0 = lane * 2;

    const float2 q = *(const float2*)(xQ + (size_t)p * 64 + c0);

    float s[NP];
    #pragma unroll
    for (int t = 0; t < NP; t++) {
        const int di = t / 3 - 1, dj = t % 3 - 1;
        const bool valid = (unsigned)(h + di) < HH && (unsigned)(w + dj) < WW;
        float2 k = make_float2(0.0f, 0.0f);
        if (valid) {
            const int pp = p + di * WW + dj;
            k = __half22float2(*(const __half2*)(xK + (size_t)pp * 576 + t * 64 + c0));
        }
        float part = k.x * q.x + k.y * q.y;
        #pragma unroll
        for (int off = 8; off >= 1; off >>= 1)
            part += __shfl_xor_sync(0xffffffffu, part, off);
        s[t] = part * (1.0f / 3.0f);
    }

    float m = s[0];
    #pragma unroll
    for (int t = 1; t < NP; t++) m = fmaxf(m, s[t]);
    float e[NP], sum = 0.0f;
    #pragma unroll
    for (int t = 0; t < NP; t++) { e[t] = expf(s[t] - m); sum += e[t]; }
    const float inv = 1.0f / sum;

    float2 acc = make_float2(0.0f, 0.0f);
    #pragma unroll
    for (int t = 0; t < NP; t++) {
        const int di = t / 3 - 1, dj = t % 3 - 1;
        const bool valid = (unsigned)(h + di) < HH && (unsigned)(w + dj) < WW;
        if (valid) {
            const int pp = p + di * WW + dj;
            const float2 v = __half22float2(*(const __half2*)(xV + (size_t)pp * 576 + t * 64 + c0));
            const float al = e[t] * inv;
            acc.x = fmaf(al, v.x, acc.x);
            acc.y = fmaf(al, v.y, acc.y);
        }
    }
    acc.x = tf32r(acc.x);
    acc.y = tf32r(acc.y);
    *(float2*)(out + (size_t)p * 64 + c0) = acc;
}

// ---------------------------------------------------------------------------
// 3x3 conv, implicit GEMM, pre-shuffled weights via cp.async ping-pong.
// Inputs pre-rounded to tf32 at producer epilogue (raw halo copy).
// grid = (W/16, H/TH, B), 256 threads.
// ---------------------------------------------------------------------------
template <int CIN, int COUT, int TH, bool ROUND>
__global__ __launch_bounds__(256) void conv_tf32(
    const float* __restrict__ in, const uint32_t* __restrict__ wfrag,
    const float* __restrict__ bias, float* __restrict__ out)
{
    constexpr int TW = 16;
    constexpr int HW2 = TW + 2;
    constexpr int PSTRIDE = 68;
    constexpr int HALO_F = (TH + 2) * HW2 * PSTRIDE;
    constexpr int NWN = COUT / 64;
    constexpr int CHUNKS = CIN / 64;
    constexpr int WTAP = 64 * COUT;            // uints per tap-chunk
    constexpr int CPW = WTAP / 4 / 256;        // cp.async per thread per tap

    extern __shared__ char smraw[];
    float*    halo = (float*)smraw;
    uint32_t* Bf   = (uint32_t*)(smraw + HALO_F * 4);   // 2 x WTAP

    const int x0 = blockIdx.x * TW;
    const int y0 = blockIdx.y * TH;
    const int b  = blockIdx.z;
    const int tid = threadIdx.x;
    const int warp = tid >> 5, lane = tid & 31;
    const int wm = warp / NWN, wn = warp % NWN;
    const int lr = lane >> 2, lc = lane & 3;

    float acc[2][8][4] = {};

    int pixoff[2][2];
    #pragma unroll
    for (int mf = 0; mf < 2; mf++)
        #pragma unroll
        for (int r8 = 0; r8 < 2; r8++) {
            int m = wm * 32 + mf * 16 + r8 * 8 + lr;
            int py = m >> 4, px = m & 15;
            pixoff[mf][r8] = (py * HW2 + px) * PSTRIDE;
        }

    for (int ch = 0; ch < CHUNKS; ch++) {
        const int cin0 = ch * 64;
        __syncthreads();   // prior chunk's halo/Bf consumers done

        // halo chunk (raw float4 copy; producer pre-rounded)
        for (int idx = tid * 4; idx < (TH + 2) * HW2 * 64; idx += 256 * 4) {
            int c = idx & 63;
            int sp = idx >> 6;
            int hy = sp / HW2, hx = sp - hy * HW2;
            int gy = y0 + hy - 1, gx = x0 + hx - 1;
            float4 v = make_float4(0.f, 0.f, 0.f, 0.f);
            if ((unsigned)gy < HH && (unsigned)gx < WW)
                v = *(const float4*)(in + (((size_t)b * HH + gy) * WW + gx) * CIN + cin0 + c);
            *(float4*)(halo + sp * PSTRIDE + c) = v;
        }

        // prime tap 0 weights
        {
            const uint32_t* src = wfrag + (size_t)(0 * CHUNKS + ch) * WTAP;
            #pragma unroll
            for (int i = 0; i < CPW; i++) {
                int o = (tid + i * 256) * 4;
                cp16(Bf + o, src + o);
            }
            cp_commit();
        }
        cp_wait0();
        __syncthreads();

        for (int t = 0; t < 9; t++) {
            if (t < 8) {
                uint32_t* Bn = Bf + ((t + 1) & 1) * WTAP;
                const uint32_t* src = wfrag + (size_t)((t + 1) * CHUNKS + ch) * WTAP;
                #pragma unroll
                for (int i = 0; i < CPW; i++) {
                    int o = (tid + i * 256) * 4;
                    cp16(Bn + o, src + o);
                }
                cp_commit();
            }

            const uint32_t* Bc = Bf + (t & 1) * WTAP;
            const int ti = t / 3, tj = t % 3;
            const int toff = (ti * HW2 + tj) * PSTRIDE;

            #pragma unroll
            for (int ks = 0; ks < 8; ks++) {
                uint32_t a[2][4];
                #pragma unroll
                for (int mf = 0; mf < 2; mf++) {
                    const float* b0 = halo + pixoff[mf][0] + toff + ks * 8 + lc;
                    const float* b1 = halo + pixoff[mf][1] + toff + ks * 8 + lc;
                    a[mf][0] = __float_as_uint(b0[0]);
                    a[mf][1] = __float_as_uint(b1[0]);
                    a[mf][2] = __float_as_uint(b0[4]);
                    a[mf][3] = __float_as_uint(b1[4]);
                }
                #pragma unroll
                for (int nf = 0; nf < 8; nf++) {
                    int sec = ks * (COUT / 8) + wn * 8 + nf;
                    uint2 bv = *(const uint2*)&Bc[sec * 64 + lane * 2];
                    uint32_t br[2] = {bv.x, bv.y};
                    mma8(acc[0][nf], a[0], br);
                    mma8(acc[1][nf], a[1], br);
                }
            }

            if (t < 8) { cp_wait0(); __syncthreads(); }
        }
    }

    #pragma unroll
    for (int mf = 0; mf < 2; mf++) {
        #pragma unroll
        for (int r8 = 0; r8 < 2; r8++) {
            int m = wm * 32 + mf * 16 + r8 * 8 + lr;
            int py = m >> 4, px = m & 15;
            int y = y0 + py, x = x0 + px;
            size_t base = (((size_t)b * HH + y) * WW + x) * COUT;
            #pragma unroll
            for (int nf = 0; nf < 8; nf++) {
                int n = wn * 64 + nf * 8 + lc * 2;
                float vx = fmaxf(acc[mf][nf][r8 * 2 + 0] + bias[n], 0.f);
                float vy = fmaxf(acc[mf][nf][r8 * 2 + 1] + bias[n + 1], 0.f);
                if (ROUND) { vx = tf32r(vx); vy = tf32r(vy); }
                *(float2*)(out + base + n) = make_float2(vx, vy);
            }
        }
    }
}

// ---------------------------------------------------------------------------
// Launch
// ---------------------------------------------------------------------------
extern "C" void kernel_launch(void* const* d_in, const int* in_sizes, int n_in,
                              void* d_out, int out_size)
{
    const float* x      = (const float*)d_in[0];
    const float* K_P    = (const float*)d_in[1];
    const float* V_P    = (const float*)d_in[2];
    const float* Q_P    = (const float*)d_in[3];
    const float* ff1_k  = (const float*)d_in[4];
    const float* ff1_b  = (const float*)d_in[5];
    const float* ff2_k  = (const float*)d_in[6];
    const float* ff2_b  = (const float*)d_in[7];
    const float* ff3_k  = (const float*)d_in[8];
    const float* ff3_b  = (const float*)d_in[9];
    float* out = (float*)d_out;

    __half *xKh, *xVh;
    float *xr, *xQ, *attn, *t1, *t2;
    uint32_t *wKf, *wVf, *wQf, *wF1f, *wc2f, *wc3f;
    cudaGetSymbolAddress((void**)&xKh,  g_xKh);
    cudaGetSymbolAddress((void**)&xVh,  g_xVh);
    cudaGetSymbolAddress((void**)&xr,   g_xr);
    cudaGetSymbolAddress((void**)&xQ,   g_xQ);
    cudaGetSymbolAddress((void**)&attn, g_attn);
    cudaGetSymbolAddress((void**)&t1,   g_t1);
    cudaGetSymbolAddress((void**)&t2,   g_t2);
    cudaGetSymbolAddress((void**)&wKf,  g_wKf);
    cudaGetSymbolAddress((void**)&wVf,  g_wVf);
    cudaGetSymbolAddress((void**)&wQf,  g_wQf);
    cudaGetSymbolAddress((void**)&wF1f, g_wF1f);
    cudaGetSymbolAddress((void**)&wc2f, g_wc2f);
    cudaGetSymbolAddress((void**)&wc3f, g_wc3f);

    const int KV_SMEM    = 128 * ASTRIDE * 4 + 2 * 4096 * 4;   // 67584
    const int G1_SMEM    = 128 * ASTRIDE * 4 + 4096 * 4;       // 51200
    const int CONV2_SMEM = 10 * 18 * 68 * 4 + 2 * 8192 * 4;    // 114496
    const int CONV3_SMEM = 18 * 18 * 68 * 4 + 2 * 4096 * 4;    // 120896

    cudaFuncSetAttribute(gemm_kv,  cudaFuncAttributeMaxDynamicSharedMemorySize, KV_SMEM);
    cudaFuncSetAttribute(gemm1<0>, cudaFuncAttributeMaxDynamicSharedMemorySize, G1_SMEM);
    cudaFuncSetAttribute(gemm1<1>, cudaFuncAttributeMaxDynamicSharedMemorySize, G1_SMEM);
    cudaFuncSetAttribute((conv_tf32<64, 128, 8, true>),   cudaFuncAttributeMaxDynamicSharedMemorySize, CONV2_SMEM);
    cudaFuncSetAttribute((conv_tf32<128, 64, 16, false>), cudaFuncAttributeMaxDynamicSharedMemorySize, CONV3_SMEM);

    // Prep
    prep_x<<<4096, 256>>>(x, xr);
    prep_w<<<896, 256>>>(K_P, V_P, Q_P, ff1_k, ff2_k, ff3_k);

    const int MT = PTOT / 128;  // 512

    // Projections
    gemm_kv<<<dim3(MT, 2), 128, KV_SMEM>>>(xr, wKf, wVf, xKh, xVh);
    gemm1<0><<<MT, 128, G1_SMEM>>>(xr, wQf, nullptr, xQ);

    // Attention
    attn_kernel<<<PTOT / 8, 256>>>(xKh, xVh, xQ, attn);

    // FFN
    gemm1<1><<<MT, 128, G1_SMEM>>>(attn, wF1f, ff1_b, t1);
    conv_tf32<64, 128, 8, true><<<dim3(WW / 16, HH / 8, BB), 256, CONV2_SMEM>>>(t1, wc2f, ff2_b, t2);
    conv_tf32<128, 64, 16, false><<<dim3(WW / 16, HH / 16, BB), 256, CONV3_SMEM>>>(t2, wc3f, ff3_b, out);
}

// round 4
// speedup vs baseline: 3.9886x; 1.0348x over previous
#include <cuda_runtime.h>
#include <cuda_fp16.h>
#include <cstdint>
#include <cstddef>

#define BB 4
#define HH 128
#define WW 128
#define DD 64
#define NP 9
#define PTOT (BB*HH*WW)        // 65536 pixels
#define ASTRIDE 68

// ---------------------------------------------------------------------------
// Scratch
// ---------------------------------------------------------------------------
__device__ __half g_xKh[(size_t)PTOT * 576];    // pair-permuted layout
__device__ __half g_xVh[(size_t)PTOT * 576];    // pair-permuted layout
__device__ float  g_xQ [(size_t)PTOT * 64];     // original layout
__device__ float  g_attn[(size_t)PTOT * 64];    // tf32-rounded
__device__ float  g_t1 [(size_t)PTOT * 64];     // tf32-rounded
__device__ float  g_t2 [(size_t)PTOT * 128];    // tf32-rounded
// fragment-ordered tf32 weights
__device__ uint32_t g_wKf[9 * 4096];
__device__ uint32_t g_wVf[9 * 4096];
__device__ uint32_t g_wQf[4096];
__device__ uint32_t g_wF1f[4096];
__device__ uint32_t g_wc2f[9 * 8192];           // [tap][sec][64]
__device__ uint32_t g_wc3f[18 * 4096];          // [tap*2+chunk][sec][64]

// ---------------------------------------------------------------------------
// helpers
// ---------------------------------------------------------------------------
__device__ __forceinline__ uint32_t tf32b(float x) {
    uint32_t u;
    asm("cvt.rna.tf32.f32 %0, %1;" : "=r"(u) : "f"(x));
    return u;
}
__device__ __forceinline__ float tf32r(float x) { return __uint_as_float(tf32b(x)); }

__device__ __forceinline__ void mma8(float* c, const uint32_t* a, const uint32_t* b) {
    asm volatile(
        "mma.sync.aligned.m16n8k8.row.col.f32.tf32.tf32.f32 "
        "{%0,%1,%2,%3}, {%4,%5,%6,%7}, {%8,%9}, {%0,%1,%2,%3};"
        : "+f"(c[0]), "+f"(c[1]), "+f"(c[2]), "+f"(c[3])
        : "r"(a[0]), "r"(a[1]), "r"(a[2]), "r"(a[3]),
          "r"(b[0]), "r"(b[1]));
}

__device__ __forceinline__ void cp16(void* dst_smem, const void* src) {
    uint32_t d = (uint32_t)__cvta_generic_to_shared(dst_smem);
    asm volatile("cp.async.cg.shared.global [%0], [%1], 16;" :: "r"(d), "l"(src) : "memory");
}
__device__ __forceinline__ void cp_commit() { asm volatile("cp.async.commit_group;" ::: "memory"); }
__device__ __forceinline__ void cp_wait0()  { asm volatile("cp.async.wait_group 0;"  ::: "memory"); }
__device__ __forceinline__ void cp_wait1()  { asm volatile("cp.async.wait_group 1;"  ::: "memory"); }

// ---------------------------------------------------------------------------
// Prep: shuffle all weights into fragment order (tf32-rounded)
// ---------------------------------------------------------------------------
__global__ __launch_bounds__(256) void prep_w(
    const float* __restrict__ K_P, const float* __restrict__ V_P,
    const float* __restrict__ Q_P, const float* __restrict__ F1,
    const float* __restrict__ W2, const float* __restrict__ W3)
{
    int i = blockIdx.x * 256 + threadIdx.x;
    if (i < 73728) {                               // K_P / V_P [64,576]
        const float* src = (i < 36864) ? K_P : V_P;
        uint32_t* dst = (i < 36864) ? g_wKf : g_wVf;
        int j = (i < 36864) ? i : i - 36864;
        int k = j / 576, n = j % 576;
        int nt = n >> 6, nl = n & 63;
        int pos = ((k >> 3) * 8 + (nl >> 3)) * 64 + (((nl & 7) << 2) | (k & 3)) * 2 + ((k & 7) >> 2);
        dst[nt * 4096 + pos] = tf32b(src[j]);
    } else if (i < 81920) {                        // Q_P / ff1 [64,64]
        int j = i - 73728;
        const float* src = (j < 4096) ? Q_P : F1;
        uint32_t* dst = (j < 4096) ? g_wQf : g_wF1f;
        int jj = j & 4095;
        int k = jj >> 6, n = jj & 63;
        int pos = ((k >> 3) * 8 + (n >> 3)) * 64 + (((n & 7) << 2) | (k & 3)) * 2 + ((k & 7) >> 2);
        dst[pos] = tf32b(src[jj]);
    } else if (i < 155648) {                       // ff2 [9][64][128]
        int j = i - 81920;
        int t = j >> 13, k = (j >> 7) & 63, n = j & 127;
        int pos = ((k >> 3) * 16 + (n >> 3)) * 64 + (((n & 7) << 2) | (k & 3)) * 2 + ((k & 7) >> 2);
        g_wc2f[t * 8192 + pos] = tf32b(W2[j]);
    } else {                                       // ff3 [9][128][64]
        int j = i - 155648;
        int t = j >> 13, k = (j >> 6) & 127, n = j & 63;
        int ch = k >> 6, kl = k & 63;
        int pos = ((kl >> 3) * 8 + (n >> 3)) * 64 + (((n & 7) << 2) | (kl & 3)) * 2 + ((kl & 7) >> 2);
        g_wc3f[(t * 2 + ch) * 4096 + pos] = tf32b(W3[j]);
    }
}

// ---------------------------------------------------------------------------
// K/V/Q projection GEMM. A[128,64] (raw fp32, cvt at hoist) x W -> out.
// grid (PTOT/128, 3): y=0 K, y=1 V (9 tiles, packed fp16), y=2 Q (1 tile, fp32).
// K/V store layout per 64-col tile: pair (nf*4+lc) stored at slot (lc*8+nf).
// ---------------------------------------------------------------------------
__global__ __launch_bounds__(128) void gemm_kvq(
    const float* __restrict__ x,
    const uint32_t* __restrict__ wK, const uint32_t* __restrict__ wV,
    const uint32_t* __restrict__ wQ,
    __half* __restrict__ outK, __half* __restrict__ outV,
    float* __restrict__ outQ)
{
    extern __shared__ char smraw[];
    float*    Ast = (float*)smraw;                          // 128*68
    uint32_t* Bf  = (uint32_t*)(smraw + 128 * ASTRIDE * 4); // 2 x 4096

    const int y = blockIdx.y;
    const uint32_t* wfrag = (y == 0) ? wK : (y == 1) ? wV : wQ;
    __half* outH          = (y == 0) ? outK : outV;
    const int NT          = (y == 2) ? 1 : 9;

    const int m0 = blockIdx.x * 128;
    const int tid = threadIdx.x;

    // stage A (raw fp32) + B tile 0
    #pragma unroll
    for (int i = 0; i < 16; i++) {
        int idx = tid + i * 128;
        int r = idx >> 4, c4 = (idx & 15) * 4;
        cp16(Ast + r * ASTRIDE + c4, x + (size_t)(m0 + r) * 64 + c4);
    }
    #pragma unroll
    for (int i = 0; i < 8; i++) {
        int o = (tid + i * 128) * 4;
        cp16(Bf + o, wfrag + o);
    }
    cp_commit();
    cp_wait0();
    __syncthreads();

    const int warp = tid >> 5, lane = tid & 31;
    const int mw = warp * 32;
    const int lr = lane >> 2, lc = lane & 3;

    // hoist all A fragments to registers, rounding fp32 -> tf32 here
    uint32_t a[8][2][4];
    #pragma unroll
    for (int ks = 0; ks < 8; ks++)
        #pragma unroll
        for (int mf = 0; mf < 2; mf++) {
            const float* base = Ast + (mw + mf * 16 + lr) * ASTRIDE + ks * 8 + lc;
            a[ks][mf][0] = tf32b(base[0]);
            a[ks][mf][1] = tf32b(base[8 * ASTRIDE]);
            a[ks][mf][2] = tf32b(base[4]);
            a[ks][mf][3] = tf32b(base[8 * ASTRIDE + 4]);
        }

    for (int nt = 0; nt < NT; nt++) {
        uint32_t* Bc = Bf + (nt & 1) * 4096;
        if (nt < NT - 1) {
            uint32_t* Bn = Bf + ((nt + 1) & 1) * 4096;
            const uint32_t* src = wfrag + (nt + 1) * 4096;
            #pragma unroll
            for (int i = 0; i < 8; i++) {
                int o = (tid + i * 128) * 4;
                cp16(Bn + o, src + o);
            }
            cp_commit();
        }

        float acc[2][8][4] = {};
        #pragma unroll
        for (int ks = 0; ks < 8; ks++)
            #pragma unroll
            for (int nf = 0; nf < 8; nf++) {
                uint2 b = *(const uint2*)&Bc[(ks * 8 + nf) * 64 + lane * 2];
                uint32_t br[2] = {b.x, b.y};
                mma8(acc[0][nf], a[ks][0], br);
                mma8(acc[1][nf], a[ks][1], br);
            }

        if (y == 2) {
            // Q epilogue: fp32, original layout
            #pragma unroll
            for (int mf = 0; mf < 2; mf++) {
                int r0 = m0 + mw + mf * 16 + lr;
                #pragma unroll
                for (int nf = 0; nf < 8; nf++) {
                    int col = nf * 8 + lc * 2;
                    *(float2*)(outQ + (size_t)r0 * 64 + col) =
                        make_float2(acc[mf][nf][0], acc[mf][nf][1]);
                    *(float2*)(outQ + (size_t)(r0 + 8) * 64 + col) =
                        make_float2(acc[mf][nf][2], acc[mf][nf][3]);
                }
            }
        } else {
            // K/V epilogue: fp16 packed. Pair (nf*4+lc) -> slot lc*8+nf.
            // Per row this thread owns 8 consecutive slots at lc*8 -> 2 STG.128.
            #pragma unroll
            for (int mf = 0; mf < 2; mf++) {
                int r0 = m0 + mw + mf * 16 + lr;
                uint32_t p0[8], p1[8];
                #pragma unroll
                for (int nf = 0; nf < 8; nf++) {
                    __half2 h0 = __floats2half2_rn(acc[mf][nf][0], acc[mf][nf][1]);
                    __half2 h1 = __floats2half2_rn(acc[mf][nf][2], acc[mf][nf][3]);
                    p0[nf] = *(uint32_t*)&h0;
                    p1[nf] = *(uint32_t*)&h1;
                }
                __half* o0 = outH + (size_t)r0 * 576 + nt * 64 + lc * 16;
                __half* o1 = outH + (size_t)(r0 + 8) * 576 + nt * 64 + lc * 16;
                *(uint4*)o0       = make_uint4(p0[0], p0[1], p0[2], p0[3]);
                *(uint4*)(o0 + 8) = make_uint4(p0[4], p0[5], p0[6], p0[7]);
                *(uint4*)o1       = make_uint4(p1[0], p1[1], p1[2], p1[3]);
                *(uint4*)(o1 + 8) = make_uint4(p1[4], p1[5], p1[6], p1[7]);
            }
        }

        if (nt < NT - 1) { cp_wait0(); __syncthreads(); }
    }
}

// ---------------------------------------------------------------------------
// ff1 GEMM: A[128,64] x W[64,64] -> fp32, bias+relu+tf32-round.
// ---------------------------------------------------------------------------
__global__ __launch_bounds__(128) void gemm_ff1(
    const float* __restrict__ A, const uint32_t* __restrict__ wfrag,
    const float* __restrict__ bias, float* __restrict__ C)
{
    extern __shared__ char smraw[];
    float*    Ast = (float*)smraw;
    uint32_t* Bf  = (uint32_t*)(smraw + 128 * ASTRIDE * 4);

    const int m0 = blockIdx.x * 128;
    const int tid = threadIdx.x;

    #pragma unroll
    for (int i = 0; i < 16; i++) {
        int idx = tid + i * 128;
        int r = idx >> 4, c4 = (idx & 15) * 4;
        cp16(Ast + r * ASTRIDE + c4, A + (size_t)(m0 + r) * 64 + c4);
    }
    #pragma unroll
    for (int i = 0; i < 8; i++) {
        int o = (tid + i * 128) * 4;
        cp16(Bf + o, wfrag + o);
    }
    cp_commit(); cp_wait0(); __syncthreads();

    const int warp = tid >> 5, lane = tid & 31;
    const int mw = warp * 32;
    const int lr = lane >> 2, lc = lane & 3;

    float acc[2][8][4] = {};
    #pragma unroll
    for (int ks = 0; ks < 8; ks++) {
        uint32_t a[2][4];
        #pragma unroll
        for (int mf = 0; mf < 2; mf++) {
            const float* base = Ast + (mw + mf * 16 + lr) * ASTRIDE + ks * 8 + lc;
            a[mf][0] = __float_as_uint(base[0]);
            a[mf][1] = __float_as_uint(base[8 * ASTRIDE]);
            a[mf][2] = __float_as_uint(base[4]);
            a[mf][3] = __float_as_uint(base[8 * ASTRIDE + 4]);
        }
        #pragma unroll
        for (int nf = 0; nf < 8; nf++) {
            uint2 b = *(const uint2*)&Bf[(ks * 8 + nf) * 64 + lane * 2];
            uint32_t br[2] = {b.x, b.y};
            mma8(acc[0][nf], a[0], br);
            mma8(acc[1][nf], a[1], br);
        }
    }

    #pragma unroll
    for (int mf = 0; mf < 2; mf++) {
        int r0 = m0 + mw + mf * 16 + lr;
        #pragma unroll
        for (int nf = 0; nf < 8; nf++) {
            int col = nf * 8 + lc * 2;
            float b0 = bias[col], b1 = bias[col + 1];
            float v0 = tf32r(fmaxf(acc[mf][nf][0] + b0, 0.f));
            float v1 = tf32r(fmaxf(acc[mf][nf][1] + b1, 0.f));
            float v2 = tf32r(fmaxf(acc[mf][nf][2] + b0, 0.f));
            float v3 = tf32r(fmaxf(acc[mf][nf][3] + b1, 0.f));
            *(float2*)(C + (size_t)r0 * 64 + col)       = make_float2(v0, v1);
            *(float2*)(C + (size_t)(r0 + 8) * 64 + col) = make_float2(v2, v3);
        }
    }
}

// ---------------------------------------------------------------------------
// Attention (fp16 K/V pair-permuted, fp32 Q orig). One warp / pixel.
// ---------------------------------------------------------------------------
__global__ __launch_bounds__(256) void attn_kernel(
    const __half* __restrict__ xK, const __half* __restrict__ xV,
    const float* __restrict__ xQ, float* __restrict__ out)
{
    const int warp = threadIdx.x >> 5;
    const int lane = threadIdx.x & 31;
    const int p = blockIdx.x * 8 + warp;

    const int hw = p & (HH * WW - 1);
    const int h = hw >> 7;
    const int w = hw & 127;
    const int c0  = lane * 2;                                // orig channels (Q, out)
    const int chp = 2 * (((lane & 3) << 3) | (lane >> 2));   // permuted offset (K/V)

    const float2 q = *(const float2*)(xQ + (size_t)p * 64 + c0);

    float s[NP];
    #pragma unroll
    for (int t = 0; t < NP; t++) {
        const int di = t / 3 - 1, dj = t % 3 - 1;
        const bool valid = (unsigned)(h + di) < HH && (unsigned)(w + dj) < WW;
        float2 k = make_float2(0.0f, 0.0f);
        if (valid) {
            const int pp = p + di * WW + dj;
            k = __half22float2(*(const __half2*)(xK + (size_t)pp * 576 + t * 64 + chp));
        }
        float part = k.x * q.x + k.y * q.y;
        #pragma unroll
        for (int off = 8; off >= 1; off >>= 1)
            part += __shfl_xor_sync(0xffffffffu, part, off);
        s[t] = part * (1.0f / 3.0f);
    }

    float m = s[0];
    #pragma unroll
    for (int t = 1; t < NP; t++) m = fmaxf(m, s[t]);
    float e[NP], sum = 0.0f;
    #pragma unroll
    for (int t = 0; t < NP; t++) { e[t] = expf(s[t] - m); sum += e[t]; }
    const float inv = 1.0f / sum;

    float2 acc = make_float2(0.0f, 0.0f);
    #pragma unroll
    for (int t = 0; t < NP; t++) {
        const int di = t / 3 - 1, dj = t % 3 - 1;
        const bool valid = (unsigned)(h + di) < HH && (unsigned)(w + dj) < WW;
        if (valid) {
            const int pp = p + di * WW + dj;
            const float2 v = __half22float2(*(const __half2*)(xV + (size_t)pp * 576 + t * 64 + chp));
            const float al = e[t] * inv;
            acc.x = fmaf(al, v.x, acc.x);
            acc.y = fmaf(al, v.y, acc.y);
        }
    }
    acc.x = tf32r(acc.x);
    acc.y = tf32r(acc.y);
    *(float2*)(out + (size_t)p * 64 + c0) = acc;
}

// ---------------------------------------------------------------------------
// 3x3 conv, implicit GEMM. TH=8 x TW=16 tile. Half-tap triple-buffered
// weight staging (cp.async, wait_group 1). MFS = m16-fragments per warp.
// conv2: COUT=128, NWN=2, MFS=2.  conv3: COUT=64, NWN=1, MFS=1.
// grid = (W/16, H/8, B), 256 threads.
// ---------------------------------------------------------------------------
template <int CIN, int COUT, int MFS, bool ROUND>
__global__ __launch_bounds__(256, 2) void conv_tf32(
    const float* __restrict__ in, const uint32_t* __restrict__ wfrag,
    const float* __restrict__ bias, float* __restrict__ out)
{
    constexpr int TH = 8, TW = 16;
    constexpr int HW2 = TW + 2;
    constexpr int PSTRIDE = 68;
    constexpr int HALO_F = (TH + 2) * HW2 * PSTRIDE;
    constexpr int NWN = COUT / 64;
    constexpr int CHUNKS = CIN / 64;
    constexpr int WTAP = 64 * COUT;            // uints per tap-chunk
    constexpr int HBUF = WTAP / 2;             // uints per half-tap
    constexpr int CPH = HBUF / 4 / 256;        // cp16 per thread per half-tap

    extern __shared__ char smraw[];
    float*    halo = (float*)smraw;
    uint32_t* Bf   = (uint32_t*)(smraw + HALO_F * 4);   // 3 x HBUF

    const int x0 = blockIdx.x * TW;
    const int y0 = blockIdx.y * TH;
    const int b  = blockIdx.z;
    const int tid = threadIdx.x;
    const int warp = tid >> 5, lane = tid & 31;
    const int wm = warp / NWN, wn = warp % NWN;
    const int lr = lane >> 2, lc = lane & 3;

    float acc[MFS][8][4] = {};

    int pixoff[MFS][2];
    #pragma unroll
    for (int mf = 0; mf < MFS; mf++)
        #pragma unroll
        for (int r8 = 0; r8 < 2; r8++) {
            int m = wm * (MFS * 16) + mf * 16 + r8 * 8 + lr;
            int py = m >> 4, px = m & 15;
            pixoff[mf][r8] = (py * HW2 + px) * PSTRIDE;
        }

    for (int ch = 0; ch < CHUNKS; ch++) {
        const int cin0 = ch * 64;
        __syncthreads();   // prior chunk fully consumed before halo overwrite

        // halo chunk (plain float4 stores; producer pre-rounded to tf32)
        for (int idx = tid * 4; idx < (TH + 2) * HW2 * 64; idx += 256 * 4) {
            int c = idx & 63;
            int sp = idx >> 6;
            int hy = sp / HW2, hx = sp - hy * HW2;
            int gy = y0 + hy - 1, gx = x0 + hx - 1;
            float4 v = make_float4(0.f, 0.f, 0.f, 0.f);
            if ((unsigned)gy < HH && (unsigned)gx < WW)
                v = *(const float4*)(in + (((size_t)b * HH + gy) * WW + gx) * CIN + cin0 + c);
            *(float4*)(halo + sp * PSTRIDE + c) = v;
        }

        // prime stage 0
        {
            const uint32_t* src = wfrag + (size_t)(0 * CHUNKS + ch) * WTAP;
            #pragma unroll
            for (int i = 0; i < CPH; i++) {
                int o = (tid + i * 256) * 4;
                cp16(Bf + o, src + o);
            }
            cp_commit();
        }

        for (int s = 0; s < 18; s++) {
            if (s < 17) {
                const int sn = s + 1;
                const int tn = sn >> 1, hn = sn & 1;
                uint32_t* Bn = Bf + (sn % 3) * HBUF;
                const uint32_t* src = wfrag + (size_t)(tn * CHUNKS + ch) * WTAP + hn * HBUF;
                #pragma unroll
                for (int i = 0; i < CPH; i++) {
                    int o = (tid + i * 256) * 4;
                    cp16(Bn + o, src + o);
                }
            }
            cp_commit();          // (empty group at s==17 keeps wait semantics uniform)
            cp_wait1();           // stage s data landed; stage s+1 may be in flight
            __syncthreads();      // covers halo stores on s==0, Bf visibility otherwise

            const uint32_t* Bc = Bf + (s % 3) * HBUF;
            const int t = s >> 1, hh = s & 1;
            const int ti = t / 3, tj = t % 3;
            const int toff = (ti * HW2 + tj) * PSTRIDE;

            #pragma unroll
            for (int kk = 0; kk < 4; kk++) {
                const int ks = hh * 4 + kk;
                uint32_t a[MFS][4];
                #pragma unroll
                for (int mf = 0; mf < MFS; mf++) {
                    const float* b0 = halo + pixoff[mf][0] + toff + ks * 8 + lc;
                    const float* b1 = halo + pixoff[mf][1] + toff + ks * 8 + lc;
                    a[mf][0] = __float_as_uint(b0[0]);
                    a[mf][1] = __float_as_uint(b1[0]);
                    a[mf][2] = __float_as_uint(b0[4]);
                    a[mf][3] = __float_as_uint(b1[4]);
                }
                #pragma unroll
                for (int nf = 0; nf < 8; nf++) {
                    int sec = kk * (COUT / 8) + wn * 8 + nf;
                    uint2 bv = *(const uint2*)&Bc[sec * 64 + lane * 2];
                    uint32_t br[2] = {bv.x, bv.y};
                    #pragma unroll
                    for (int mf = 0; mf < MFS; mf++)
                        mma8(acc[mf][nf], a[mf], br);
                }
            }
        }
    }

    #pragma unroll
    for (int mf = 0; mf < MFS; mf++) {
        #pragma unroll
        for (int r8 = 0; r8 < 2; r8++) {
            int m = wm * (MFS * 16) + mf * 16 + r8 * 8 + lr;
            int py = m >> 4, px = m & 15;
            int y = y0 + py, x = x0 + px;
            size_t base = (((size_t)b * HH + y) * WW + x) * COUT;
            #pragma unroll
            for (int nf = 0; nf < 8; nf++) {
                int n = wn * 64 + nf * 8 + lc * 2;
                float vx = fmaxf(acc[mf][nf][r8 * 2 + 0] + bias[n], 0.f);
                float vy = fmaxf(acc[mf][nf][r8 * 2 + 1] + bias[n + 1], 0.f);
                if (ROUND) { vx = tf32r(vx); vy = tf32r(vy); }
                *(float2*)(out + base + n) = make_float2(vx, vy);
            }
        }
    }
}

// ---------------------------------------------------------------------------
// Launch
// ---------------------------------------------------------------------------
extern "C" void kernel_launch(void* const* d_in, const int* in_sizes, int n_in,
                              void* d_out, int out_size)
{
    const float* x      = (const float*)d_in[0];
    const float* K_P    = (const float*)d_in[1];
    const float* V_P    = (const float*)d_in[2];
    const float* Q_P    = (const float*)d_in[3];
    const float* ff1_k  = (const float*)d_in[4];
    const float* ff1_b  = (const float*)d_in[5];
    const float* ff2_k  = (const float*)d_in[6];
    const float* ff2_b  = (const float*)d_in[7];
    const float* ff3_k  = (const float*)d_in[8];
    const float* ff3_b  = (const float*)d_in[9];
    float* out = (float*)d_out;

    __half *xKh, *xVh;
    float *xQ, *attn, *t1, *t2;
    uint32_t *wKf, *wVf, *wQf, *wF1f, *wc2f, *wc3f;
    cudaGetSymbolAddress((void**)&xKh,  g_xKh);
    cudaGetSymbolAddress((void**)&xVh,  g_xVh);
    cudaGetSymbolAddress((void**)&xQ,   g_xQ);
    cudaGetSymbolAddress((void**)&attn, g_attn);
    cudaGetSymbolAddress((void**)&t1,   g_t1);
    cudaGetSymbolAddress((void**)&t2,   g_t2);
    cudaGetSymbolAddress((void**)&wKf,  g_wKf);
    cudaGetSymbolAddress((void**)&wVf,  g_wVf);
    cudaGetSymbolAddress((void**)&wQf,  g_wQf);
    cudaGetSymbolAddress((void**)&wF1f, g_wF1f);
    cudaGetSymbolAddress((void**)&wc2f, g_wc2f);
    cudaGetSymbolAddress((void**)&wc3f, g_wc3f);

    const int KV_SMEM    = 128 * ASTRIDE * 4 + 2 * 4096 * 4;          // 67584
    const int G1_SMEM    = 128 * ASTRIDE * 4 + 4096 * 4;              // 51200
    const int CONV2_SMEM = 10 * 18 * 68 * 4 + 3 * 4096 * 4;           // 98112
    const int CONV3_SMEM = 10 * 18 * 68 * 4 + 3 * 2048 * 4;           // 73536

    cudaFuncSetAttribute(gemm_kvq, cudaFuncAttributeMaxDynamicSharedMemorySize, KV_SMEM);
    cudaFuncSetAttribute(gemm_ff1, cudaFuncAttributeMaxDynamicSharedMemorySize, G1_SMEM);
    cudaFuncSetAttribute((conv_tf32<64, 128, 2, true>),  cudaFuncAttributeMaxDynamicSharedMemorySize, CONV2_SMEM);
    cudaFuncSetAttribute((conv_tf32<128, 64, 1, false>), cudaFuncAttributeMaxDynamicSharedMemorySize, CONV3_SMEM);

    // Prep (weights only; x is rounded at the A-register hoist)
    prep_w<<<896, 256>>>(K_P, V_P, Q_P, ff1_k, ff2_k, ff3_k);

    const int MT = PTOT / 128;  // 512

    // Projections: K, V, Q in one launch
    gemm_kvq<<<dim3(MT, 3), 128, KV_SMEM>>>(x, wKf, wVf, wQf, xKh, xVh, xQ);

    // Attention
    attn_kernel<<<PTOT / 8, 256>>>(xKh, xVh, xQ, attn);

    // FFN
    gemm_ff1<<<MT, 128, G1_SMEM>>>(attn, wF1f, ff1_b, t1);
    conv_tf32<64, 128, 2, true><<<dim3(WW / 16, HH / 8, BB), 256, CONV2_SMEM>>>(t1, wc2f, ff2_b, t2);
    conv_tf32<128, 64, 1, false><<<dim3(WW / 16, HH / 8, BB), 256, CONV3_SMEM>>>(t2, wc3f, ff3_b, out);
}

// round 5
// speedup vs baseline: 4.1043x; 1.0290x over previous
#include <cuda_runtime.h>
#include <cuda_fp16.h>
#include <cstdint>
#include <cstddef>

#define BB 4
#define HH 128
#define WW 128
#define DD 64
#define NP 9
#define PTOT (BB*HH*WW)        // 65536 pixels
#define ASTRIDE 68

// ---------------------------------------------------------------------------
// Scratch
// ---------------------------------------------------------------------------
__device__ __half g_xKh[(size_t)PTOT * 576];    // pair-permuted layout
__device__ __half g_xVh[(size_t)PTOT * 576];    // pair-permuted layout
__device__ float  g_xQ [(size_t)PTOT * 64];     // original layout
__device__ float  g_t1 [(size_t)PTOT * 64];     // tf32-rounded
__device__ float  g_t2 [(size_t)PTOT * 128];    // tf32-rounded
// fragment-ordered tf32 weights
__device__ uint32_t g_wKf[9 * 4096];
__device__ uint32_t g_wVf[9 * 4096];
__device__ uint32_t g_wQf[4096];
__device__ uint32_t g_wF1f[4096];
__device__ uint32_t g_wc2f[9 * 8192];           // [tap][sec][64]
__device__ uint32_t g_wc3f[18 * 4096];          // [tap*2+chunk][sec][64]

// ---------------------------------------------------------------------------
// helpers
// ---------------------------------------------------------------------------
__device__ __forceinline__ uint32_t tf32b(float x) {
    uint32_t u;
    asm("cvt.rna.tf32.f32 %0, %1;" : "=r"(u) : "f"(x));
    return u;
}
__device__ __forceinline__ float tf32r(float x) { return __uint_as_float(tf32b(x)); }

__device__ __forceinline__ void mma8(float* c, const uint32_t* a, const uint32_t* b) {
    asm volatile(
        "mma.sync.aligned.m16n8k8.row.col.f32.tf32.tf32.f32 "
        "{%0,%1,%2,%3}, {%4,%5,%6,%7}, {%8,%9}, {%0,%1,%2,%3};"
        : "+f"(c[0]), "+f"(c[1]), "+f"(c[2]), "+f"(c[3])
        : "r"(a[0]), "r"(a[1]), "r"(a[2]), "r"(a[3]),
          "r"(b[0]), "r"(b[1]));
}

__device__ __forceinline__ void cp16(void* dst_smem, const void* src) {
    uint32_t d = (uint32_t)__cvta_generic_to_shared(dst_smem);
    asm volatile("cp.async.cg.shared.global [%0], [%1], 16;" :: "r"(d), "l"(src) : "memory");
}
__device__ __forceinline__ void cp_commit() { asm volatile("cp.async.commit_group;" ::: "memory"); }
__device__ __forceinline__ void cp_wait0()  { asm volatile("cp.async.wait_group 0;"  ::: "memory"); }
__device__ __forceinline__ void cp_wait1()  { asm volatile("cp.async.wait_group 1;"  ::: "memory"); }

// ---------------------------------------------------------------------------
// Prep: shuffle all weights into fragment order (tf32-rounded)
// ---------------------------------------------------------------------------
__global__ __launch_bounds__(256) void prep_w(
    const float* __restrict__ K_P, const float* __restrict__ V_P,
    const float* __restrict__ Q_P, const float* __restrict__ F1,
    const float* __restrict__ W2, const float* __restrict__ W3)
{
    int i = blockIdx.x * 256 + threadIdx.x;
    if (i < 73728) {                               // K_P / V_P [64,576]
        const float* src = (i < 36864) ? K_P : V_P;
        uint32_t* dst = (i < 36864) ? g_wKf : g_wVf;
        int j = (i < 36864) ? i : i - 36864;
        int k = j / 576, n = j % 576;
        int nt = n >> 6, nl = n & 63;
        int pos = ((k >> 3) * 8 + (nl >> 3)) * 64 + (((nl & 7) << 2) | (k & 3)) * 2 + ((k & 7) >> 2);
        dst[nt * 4096 + pos] = tf32b(src[j]);
    } else if (i < 81920) {                        // Q_P / ff1 [64,64]
        int j = i - 73728;
        const float* src = (j < 4096) ? Q_P : F1;
        uint32_t* dst = (j < 4096) ? g_wQf : g_wF1f;
        int jj = j & 4095;
        int k = jj >> 6, n = jj & 63;
        int pos = ((k >> 3) * 8 + (n >> 3)) * 64 + (((n & 7) << 2) | (k & 3)) * 2 + ((k & 7) >> 2);
        dst[pos] = tf32b(src[jj]);
    } else if (i < 155648) {                       // ff2 [9][64][128]
        int j = i - 81920;
        int t = j >> 13, k = (j >> 7) & 63, n = j & 127;
        int pos = ((k >> 3) * 16 + (n >> 3)) * 64 + (((n & 7) << 2) | (k & 3)) * 2 + ((k & 7) >> 2);
        g_wc2f[t * 8192 + pos] = tf32b(W2[j]);
    } else {                                       // ff3 [9][128][64]
        int j = i - 155648;
        int t = j >> 13, k = (j >> 6) & 127, n = j & 63;
        int ch = k >> 6, kl = k & 63;
        int pos = ((kl >> 3) * 8 + (n >> 3)) * 64 + (((n & 7) << 2) | (kl & 3)) * 2 + ((kl & 7) >> 2);
        g_wc3f[(t * 2 + ch) * 4096 + pos] = tf32b(W3[j]);
    }
}

// ---------------------------------------------------------------------------
// K/V/Q projection GEMM. A[128,64] (raw fp32, cvt at hoist) x W -> out.
// grid (PTOT/128, 3): y=0 K, y=1 V (9 tiles, packed fp16), y=2 Q (1 tile, fp32).
// ---------------------------------------------------------------------------
__global__ __launch_bounds__(128) void gemm_kvq(
    const float* __restrict__ x,
    const uint32_t* __restrict__ wK, const uint32_t* __restrict__ wV,
    const uint32_t* __restrict__ wQ,
    __half* __restrict__ outK, __half* __restrict__ outV,
    float* __restrict__ outQ)
{
    extern __shared__ char smraw[];
    float*    Ast = (float*)smraw;                          // 128*68
    uint32_t* Bf  = (uint32_t*)(smraw + 128 * ASTRIDE * 4); // 2 x 4096

    const int y = blockIdx.y;
    const uint32_t* wfrag = (y == 0) ? wK : (y == 1) ? wV : wQ;
    __half* outH          = (y == 0) ? outK : outV;
    const int NT          = (y == 2) ? 1 : 9;

    const int m0 = blockIdx.x * 128;
    const int tid = threadIdx.x;

    #pragma unroll
    for (int i = 0; i < 16; i++) {
        int idx = tid + i * 128;
        int r = idx >> 4, c4 = (idx & 15) * 4;
        cp16(Ast + r * ASTRIDE + c4, x + (size_t)(m0 + r) * 64 + c4);
    }
    #pragma unroll
    for (int i = 0; i < 8; i++) {
        int o = (tid + i * 128) * 4;
        cp16(Bf + o, wfrag + o);
    }
    cp_commit();
    cp_wait0();
    __syncthreads();

    const int warp = tid >> 5, lane = tid & 31;
    const int mw = warp * 32;
    const int lr = lane >> 2, lc = lane & 3;

    // hoist all A fragments to registers, rounding fp32 -> tf32 here
    uint32_t a[8][2][4];
    #pragma unroll
    for (int ks = 0; ks < 8; ks++)
        #pragma unroll
        for (int mf = 0; mf < 2; mf++) {
            const float* base = Ast + (mw + mf * 16 + lr) * ASTRIDE + ks * 8 + lc;
            a[ks][mf][0] = tf32b(base[0]);
            a[ks][mf][1] = tf32b(base[8 * ASTRIDE]);
            a[ks][mf][2] = tf32b(base[4]);
            a[ks][mf][3] = tf32b(base[8 * ASTRIDE + 4]);
        }

    for (int nt = 0; nt < NT; nt++) {
        uint32_t* Bc = Bf + (nt & 1) * 4096;
        if (nt < NT - 1) {
            uint32_t* Bn = Bf + ((nt + 1) & 1) * 4096;
            const uint32_t* src = wfrag + (nt + 1) * 4096;
            #pragma unroll
            for (int i = 0; i < 8; i++) {
                int o = (tid + i * 128) * 4;
                cp16(Bn + o, src + o);
            }
            cp_commit();
        }

        float acc[2][8][4] = {};
        #pragma unroll
        for (int ks = 0; ks < 8; ks++)
            #pragma unroll
            for (int nf = 0; nf < 8; nf++) {
                uint2 b = *(const uint2*)&Bc[(ks * 8 + nf) * 64 + lane * 2];
                uint32_t br[2] = {b.x, b.y};
                mma8(acc[0][nf], a[ks][0], br);
                mma8(acc[1][nf], a[ks][1], br);
            }

        if (y == 2) {
            #pragma unroll
            for (int mf = 0; mf < 2; mf++) {
                int r0 = m0 + mw + mf * 16 + lr;
                #pragma unroll
                for (int nf = 0; nf < 8; nf++) {
                    int col = nf * 8 + lc * 2;
                    *(float2*)(outQ + (size_t)r0 * 64 + col) =
                        make_float2(acc[mf][nf][0], acc[mf][nf][1]);
                    *(float2*)(outQ + (size_t)(r0 + 8) * 64 + col) =
                        make_float2(acc[mf][nf][2], acc[mf][nf][3]);
                }
            }
        } else {
            // K/V epilogue: fp16 packed. Pair (nf*4+lc) -> slot lc*8+nf.
            #pragma unroll
            for (int mf = 0; mf < 2; mf++) {
                int r0 = m0 + mw + mf * 16 + lr;
                uint32_t p0[8], p1[8];
                #pragma unroll
                for (int nf = 0; nf < 8; nf++) {
                    __half2 h0 = __floats2half2_rn(acc[mf][nf][0], acc[mf][nf][1]);
                    __half2 h1 = __floats2half2_rn(acc[mf][nf][2], acc[mf][nf][3]);
                    p0[nf] = *(uint32_t*)&h0;
                    p1[nf] = *(uint32_t*)&h1;
                }
                __half* o0 = outH + (size_t)r0 * 576 + nt * 64 + lc * 16;
                __half* o1 = outH + (size_t)(r0 + 8) * 576 + nt * 64 + lc * 16;
                *(uint4*)o0       = make_uint4(p0[0], p0[1], p0[2], p0[3]);
                *(uint4*)(o0 + 8) = make_uint4(p0[4], p0[5], p0[6], p0[7]);
                *(uint4*)o1       = make_uint4(p1[0], p1[1], p1[2], p1[3]);
                *(uint4*)(o1 + 8) = make_uint4(p1[4], p1[5], p1[6], p1[7]);
            }
        }

        if (nt < NT - 1) { cp_wait0(); __syncthreads(); }
    }
}

// ---------------------------------------------------------------------------
// Fused attention + ff1. 512 blocks x 256 threads, 128 pixels per block.
// Phase 1: warp-per-pixel attention (16 px/warp), results -> smem Ast (tf32).
// Phase 2: ff1 MMA (8 warps x m16 frag), bias+relu+tf32r -> t1.
// ---------------------------------------------------------------------------
__global__ __launch_bounds__(256) void attn_ff1(
    const __half* __restrict__ xK, const __half* __restrict__ xV,
    const float* __restrict__ xQ, const uint32_t* __restrict__ wF1,
    const float* __restrict__ bias, float* __restrict__ t1)
{
    extern __shared__ char smraw[];
    float*    Ast = (float*)smraw;                          // 128*68
    uint32_t* Bf  = (uint32_t*)(smraw + 128 * ASTRIDE * 4); // 4096

    const int tid = threadIdx.x;
    const int warp = tid >> 5;
    const int lane = tid & 31;
    const int pbase = blockIdx.x * 128;

    // stage ff1 weights (overlaps with phase 1)
    #pragma unroll
    for (int i = 0; i < 4; i++) {
        int o = (tid + i * 256) * 4;
        cp16(Bf + o, wF1 + o);
    }
    cp_commit();

    const int c0  = lane * 2;                                // orig channels
    const int chp = 2 * (((lane & 3) << 3) | (lane >> 2));   // permuted (K/V)

    // Phase 1: attention, 16 pixels per warp
    for (int it = 0; it < 16; it++) {
        const int pl = warp * 16 + it;      // local pixel 0..127
        const int p = pbase + pl;
        const int hw = p & (HH * WW - 1);
        const int h = hw >> 7;
        const int w = hw & 127;

        const float2 q = *(const float2*)(xQ + (size_t)p * 64 + c0);

        float s[NP];
        #pragma unroll
        for (int t = 0; t < NP; t++) {
            const int di = t / 3 - 1, dj = t % 3 - 1;
            const bool valid = (unsigned)(h + di) < HH && (unsigned)(w + dj) < WW;
            float2 k = make_float2(0.0f, 0.0f);
            if (valid) {
                const int pp = p + di * WW + dj;
                k = __half22float2(*(const __half2*)(xK + (size_t)pp * 576 + t * 64 + chp));
            }
            float part = k.x * q.x + k.y * q.y;
            #pragma unroll
            for (int off = 8; off >= 1; off >>= 1)
                part += __shfl_xor_sync(0xffffffffu, part, off);
            s[t] = part * (1.0f / 3.0f);
        }

        float m = s[0];
        #pragma unroll
        for (int t = 1; t < NP; t++) m = fmaxf(m, s[t]);
        float e[NP], sum = 0.0f;
        #pragma unroll
        for (int t = 0; t < NP; t++) { e[t] = expf(s[t] - m); sum += e[t]; }
        const float inv = 1.0f / sum;

        float2 acc = make_float2(0.0f, 0.0f);
        #pragma unroll
        for (int t = 0; t < NP; t++) {
            const int di = t / 3 - 1, dj = t % 3 - 1;
            const bool valid = (unsigned)(h + di) < HH && (unsigned)(w + dj) < WW;
            if (valid) {
                const int pp = p + di * WW + dj;
                const float2 v = __half22float2(*(const __half2*)(xV + (size_t)pp * 576 + t * 64 + chp));
                const float al = e[t] * inv;
                acc.x = fmaf(al, v.x, acc.x);
                acc.y = fmaf(al, v.y, acc.y);
            }
        }
        // tf32-rounded into smem A tile (orig channel order)
        Ast[pl * ASTRIDE + c0]     = tf32r(acc.x);
        Ast[pl * ASTRIDE + c0 + 1] = tf32r(acc.y);
    }

    cp_wait0();
    __syncthreads();

    // Phase 2: ff1 GEMM. 8 warps, warp handles m-frag = warp (16 px).
    const int lr = lane >> 2, lc = lane & 3;
    const int mw = warp * 16;

    float acc[8][4] = {};
    #pragma unroll
    for (int ks = 0; ks < 8; ks++) {
        uint32_t a[4];
        const float* base = Ast + (mw + lr) * ASTRIDE + ks * 8 + lc;
        a[0] = __float_as_uint(base[0]);
        a[1] = __float_as_uint(base[8 * ASTRIDE]);
        a[2] = __float_as_uint(base[4]);
        a[3] = __float_as_uint(base[8 * ASTRIDE + 4]);
        #pragma unroll
        for (int nf = 0; nf < 8; nf++) {
            uint2 b = *(const uint2*)&Bf[(ks * 8 + nf) * 64 + lane * 2];
            uint32_t br[2] = {b.x, b.y};
            mma8(acc[nf], a, br);
        }
    }

    const int r0 = pbase + mw + lr;
    #pragma unroll
    for (int nf = 0; nf < 8; nf++) {
        int col = nf * 8 + lc * 2;
        float b0 = bias[col], b1 = bias[col + 1];
        float v0 = tf32r(fmaxf(acc[nf][0] + b0, 0.f));
        float v1 = tf32r(fmaxf(acc[nf][1] + b1, 0.f));
        float v2 = tf32r(fmaxf(acc[nf][2] + b0, 0.f));
        float v3 = tf32r(fmaxf(acc[nf][3] + b1, 0.f));
        *(float2*)(t1 + (size_t)r0 * 64 + col)       = make_float2(v0, v1);
        *(float2*)(t1 + (size_t)(r0 + 8) * 64 + col) = make_float2(v2, v3);
    }
}

// ---------------------------------------------------------------------------
// 3x3 conv, implicit GEMM. TH=8 x TW=16 tile, 128 threads (4 warps).
// conv2: NWN=2, MFS=4.  conv3: NWN=1, MFS=2.  Half-tap triple-buffered weights.
// grid = (W/16, H/8, B)
// ---------------------------------------------------------------------------
template <int CIN, int COUT, int MFS, bool ROUND>
__global__ __launch_bounds__(128, 2) void conv_tf32(
    const float* __restrict__ in, const uint32_t* __restrict__ wfrag,
    const float* __restrict__ bias, float* __restrict__ out)
{
    constexpr int TH = 8, TW = 16;
    constexpr int HW2 = TW + 2;
    constexpr int PSTRIDE = 68;
    constexpr int HALO_F = (TH + 2) * HW2 * PSTRIDE;
    constexpr int NWN = COUT / 64;
    constexpr int CHUNKS = CIN / 64;
    constexpr int WTAP = 64 * COUT;            // uints per tap-chunk
    constexpr int HBUF = WTAP / 2;             // uints per half-tap
    constexpr int CPH = HBUF / 4 / 128;        // cp16 per thread per half-tap

    extern __shared__ char smraw[];
    float*    halo = (float*)smraw;
    uint32_t* Bf   = (uint32_t*)(smraw + HALO_F * 4);   // 3 x HBUF

    const int x0 = blockIdx.x * TW;
    const int y0 = blockIdx.y * TH;
    const int b  = blockIdx.z;
    const int tid = threadIdx.x;
    const int warp = tid >> 5, lane = tid & 31;
    const int wm = warp / NWN, wn = warp % NWN;
    const int lr = lane >> 2, lc = lane & 3;

    float acc[MFS][8][4] = {};

    int pixoff[MFS][2];
    #pragma unroll
    for (int mf = 0; mf < MFS; mf++)
        #pragma unroll
        for (int r8 = 0; r8 < 2; r8++) {
            int m = wm * (MFS * 16) + mf * 16 + r8 * 8 + lr;
            int py = m >> 4, px = m & 15;
            pixoff[mf][r8] = (py * HW2 + px) * PSTRIDE;
        }

    for (int ch = 0; ch < CHUNKS; ch++) {
        const int cin0 = ch * 64;
        __syncthreads();   // prior chunk fully consumed before halo overwrite

        for (int idx = tid * 4; idx < (TH + 2) * HW2 * 64; idx += 128 * 4) {
            int c = idx & 63;
            int sp = idx >> 6;
            int hy = sp / HW2, hx = sp - hy * HW2;
            int gy = y0 + hy - 1, gx = x0 + hx - 1;
            float4 v = make_float4(0.f, 0.f, 0.f, 0.f);
            if ((unsigned)gy < HH && (unsigned)gx < WW)
                v = *(const float4*)(in + (((size_t)b * HH + gy) * WW + gx) * CIN + cin0 + c);
            *(float4*)(halo + sp * PSTRIDE + c) = v;
        }

        // prime stage 0
        {
            const uint32_t* src = wfrag + (size_t)(0 * CHUNKS + ch) * WTAP;
            #pragma unroll
            for (int i = 0; i < CPH; i++) {
                int o = (tid + i * 128) * 4;
                cp16(Bf + o, src + o);
            }
            cp_commit();
        }

        for (int s = 0; s < 18; s++) {
            if (s < 17) {
                const int sn = s + 1;
                const int tn = sn >> 1, hn = sn & 1;
                uint32_t* Bn = Bf + (sn % 3) * HBUF;
                const uint32_t* src = wfrag + (size_t)(tn * CHUNKS + ch) * WTAP + hn * HBUF;
                #pragma unroll
                for (int i = 0; i < CPH; i++) {
                    int o = (tid + i * 128) * 4;
                    cp16(Bn + o, src + o);
                }
            }
            cp_commit();
            cp_wait1();
            __syncthreads();

            const uint32_t* Bc = Bf + (s % 3) * HBUF;
            const int t = s >> 1, hh = s & 1;
            const int ti = t / 3, tj = t % 3;
            const int toff = (ti * HW2 + tj) * PSTRIDE;

            #pragma unroll
            for (int kk = 0; kk < 4; kk++) {
                const int ks = hh * 4 + kk;
                uint32_t a[MFS][4];
                #pragma unroll
                for (int mf = 0; mf < MFS; mf++) {
                    const float* b0 = halo + pixoff[mf][0] + toff + ks * 8 + lc;
                    const float* b1 = halo + pixoff[mf][1] + toff + ks * 8 + lc;
                    a[mf][0] = __float_as_uint(b0[0]);
                    a[mf][1] = __float_as_uint(b1[0]);
                    a[mf][2] = __float_as_uint(b0[4]);
                    a[mf][3] = __float_as_uint(b1[4]);
                }
                #pragma unroll
                for (int nf = 0; nf < 8; nf++) {
                    int sec = kk * (COUT / 8) + wn * 8 + nf;
                    uint2 bv = *(const uint2*)&Bc[sec * 64 + lane * 2];
                    uint32_t br[2] = {bv.x, bv.y};
                    #pragma unroll
                    for (int mf = 0; mf < MFS; mf++)
                        mma8(acc[mf][nf], a[mf], br);
                }
            }
        }
    }

    #pragma unroll
    for (int mf = 0; mf < MFS; mf++) {
        #pragma unroll
        for (int r8 = 0; r8 < 2; r8++) {
            int m = wm * (MFS * 16) + mf * 16 + r8 * 8 + lr;
            int py = m >> 4, px = m & 15;
            int y = y0 + py, x = x0 + px;
            size_t base = (((size_t)b * HH + y) * WW + x) * COUT;
            #pragma unroll
            for (int nf = 0; nf < 8; nf++) {
                int n = wn * 64 + nf * 8 + lc * 2;
                float vx = fmaxf(acc[mf][nf][r8 * 2 + 0] + bias[n], 0.f);
                float vy = fmaxf(acc[mf][nf][r8 * 2 + 1] + bias[n + 1], 0.f);
                if (ROUND) { vx = tf32r(vx); vy = tf32r(vy); }
                *(float2*)(out + base + n) = make_float2(vx, vy);
            }
        }
    }
}

// ---------------------------------------------------------------------------
// Launch
// ---------------------------------------------------------------------------
extern "C" void kernel_launch(void* const* d_in, const int* in_sizes, int n_in,
                              void* d_out, int out_size)
{
    const float* x      = (const float*)d_in[0];
    const float* K_P    = (const float*)d_in[1];
    const float* V_P    = (const float*)d_in[2];
    const float* Q_P    = (const float*)d_in[3];
    const float* ff1_k  = (const float*)d_in[4];
    const float* ff1_b  = (const float*)d_in[5];
    const float* ff2_k  = (const float*)d_in[6];
    const float* ff2_b  = (const float*)d_in[7];
    const float* ff3_k  = (const float*)d_in[8];
    const float* ff3_b  = (const float*)d_in[9];
    float* out = (float*)d_out;

    __half *xKh, *xVh;
    float *xQ, *t1, *t2;
    uint32_t *wKf, *wVf, *wQf, *wF1f, *wc2f, *wc3f;
    cudaGetSymbolAddress((void**)&xKh,  g_xKh);
    cudaGetSymbolAddress((void**)&xVh,  g_xVh);
    cudaGetSymbolAddress((void**)&xQ,   g_xQ);
    cudaGetSymbolAddress((void**)&t1,   g_t1);
    cudaGetSymbolAddress((void**)&t2,   g_t2);
    cudaGetSymbolAddress((void**)&wKf,  g_wKf);
    cudaGetSymbolAddress((void**)&wVf,  g_wVf);
    cudaGetSymbolAddress((void**)&wQf,  g_wQf);
    cudaGetSymbolAddress((void**)&wF1f, g_wF1f);
    cudaGetSymbolAddress((void**)&wc2f, g_wc2f);
    cudaGetSymbolAddress((void**)&wc3f, g_wc3f);

    const int KV_SMEM    = 128 * ASTRIDE * 4 + 2 * 4096 * 4;          // 67584
    const int ATTN_SMEM  = 128 * ASTRIDE * 4 + 4096 * 4;              // 51200
    const int CONV2_SMEM = 10 * 18 * 68 * 4 + 3 * 4096 * 4;           // 98112
    const int CONV3_SMEM = 10 * 18 * 68 * 4 + 3 * 2048 * 4;           // 73536

    cudaFuncSetAttribute(gemm_kvq, cudaFuncAttributeMaxDynamicSharedMemorySize, KV_SMEM);
    cudaFuncSetAttribute(attn_ff1, cudaFuncAttributeMaxDynamicSharedMemorySize, ATTN_SMEM);
    cudaFuncSetAttribute((conv_tf32<64, 128, 4, true>),  cudaFuncAttributeMaxDynamicSharedMemorySize, CONV2_SMEM);
    cudaFuncSetAttribute((conv_tf32<128, 64, 2, false>), cudaFuncAttributeMaxDynamicSharedMemorySize, CONV3_SMEM);

    prep_w<<<896, 256>>>(K_P, V_P, Q_P, ff1_k, ff2_k, ff3_k);

    const int MT = PTOT / 128;  // 512

    // Projections: K, V, Q in one launch
    gemm_kvq<<<dim3(MT, 3), 128, KV_SMEM>>>(x, wKf, wVf, wQf, xKh, xVh, xQ);

    // Attention + ff1 fused
    attn_ff1<<<MT, 256, ATTN_SMEM>>>(xKh, xVh, xQ, wF1f, ff1_b, t1);

    // Convs
    conv_tf32<64, 128, 4, true><<<dim3(WW / 16, HH / 8, BB), 128, CONV2_SMEM>>>(t1, wc2f, ff2_b, t2);
    conv_tf32<128, 64, 2, false><<<dim3(WW / 16, HH / 8, BB), 128, CONV3_SMEM>>>(t2, wc3f, ff3_b, out);
}

// round 6
// speedup vs baseline: 4.4787x; 1.0912x over previous
#include <cuda_runtime.h>
#include <cstdint>
#include <cstddef>

#define BB 4
#define HH 128
#define WW 128
#define NP 9
#define PTOT (BB*HH*WW)

// ---------------------------------------------------------------------------
// Scratch
// ---------------------------------------------------------------------------
__device__ float  g_t1 [(size_t)PTOT * 64];     // tf32-rounded
__device__ float  g_t2 [(size_t)PTOT * 128];    // tf32-rounded
// fragment-ordered tf32 weights
__device__ uint32_t g_wKf[9 * 4096];
__device__ uint32_t g_wVf[9 * 4096];
__device__ uint32_t g_wQf[4096];
__device__ uint32_t g_wF1f[4096];
__device__ uint32_t g_wc2f[9 * 8192];           // [tap][sec][64]
__device__ uint32_t g_wc3f[18 * 4096];          // [tap*2+chunk][sec][64]

// ---------------------------------------------------------------------------
// helpers
// ---------------------------------------------------------------------------
__device__ __forceinline__ uint32_t tf32b(float x) {
    uint32_t u;
    asm("cvt.rna.tf32.f32 %0, %1;" : "=r"(u) : "f"(x));
    return u;
}
__device__ __forceinline__ float tf32r(float x) { return __uint_as_float(tf32b(x)); }

__device__ __forceinline__ void mma8(float* c, const uint32_t* a, const uint32_t* b) {
    asm volatile(
        "mma.sync.aligned.m16n8k8.row.col.f32.tf32.tf32.f32 "
        "{%0,%1,%2,%3}, {%4,%5,%6,%7}, {%8,%9}, {%0,%1,%2,%3};"
        : "+f"(c[0]), "+f"(c[1]), "+f"(c[2]), "+f"(c[3])
        : "r"(a[0]), "r"(a[1]), "r"(a[2]), "r"(a[3]),
          "r"(b[0]), "r"(b[1]));
}

__device__ __forceinline__ void cp16(void* dst_smem, const void* src) {
    uint32_t d = (uint32_t)__cvta_generic_to_shared(dst_smem);
    asm volatile("cp.async.cg.shared.global [%0], [%1], 16;" :: "r"(d), "l"(src) : "memory");
}
__device__ __forceinline__ void cp_commit() { asm volatile("cp.async.commit_group;" ::: "memory"); }
__device__ __forceinline__ void cp_wait0()  { asm volatile("cp.async.wait_group 0;"  ::: "memory"); }

// 128px x 64 x 64 warp-tile GEMM step: warp m-frag 16 rows, 8 n-frags.
// A0/A8: smem row pointers (rows lr, lr+8) already offset by +lc.
// Bl: fragment-ordered B section base + lane*2.
__device__ __forceinline__ void gemm64(float (&acc)[8][4], const uint32_t* Bl,
                                       const float* A0, const float* A8)
{
    #pragma unroll
    for (int ks = 0; ks < 8; ks++) {
        uint32_t a[4];
        a[0] = __float_as_uint(A0[ks * 8]);
        a[1] = __float_as_uint(A8[ks * 8]);
        a[2] = __float_as_uint(A0[ks * 8 + 4]);
        a[3] = __float_as_uint(A8[ks * 8 + 4]);
        #pragma unroll
        for (int nf = 0; nf < 8; nf++) {
            uint2 bv = *(const uint2*)&Bl[(ks * 8 + nf) * 64];
            uint32_t br[2] = {bv.x, bv.y};
            mma8(acc[nf], a, br);
        }
    }
}

// ---------------------------------------------------------------------------
// Prep: shuffle all weights into fragment order (tf32-rounded)
// ---------------------------------------------------------------------------
__global__ __launch_bounds__(256) void prep_w(
    const float* __restrict__ K_P, const float* __restrict__ V_P,
    const float* __restrict__ Q_P, const float* __restrict__ F1,
    const float* __restrict__ W2, const float* __restrict__ W3)
{
    int i = blockIdx.x * 256 + threadIdx.x;
    if (i < 73728) {                               // K_P / V_P [64,576]
        const float* src = (i < 36864) ? K_P : V_P;
        uint32_t* dst = (i < 36864) ? g_wKf : g_wVf;
        int j = (i < 36864) ? i : i - 36864;
        int k = j / 576, n = j % 576;
        int nt = n >> 6, nl = n & 63;
        int pos = ((k >> 3) * 8 + (nl >> 3)) * 64 + (((nl & 7) << 2) | (k & 3)) * 2 + ((k & 7) >> 2);
        dst[nt * 4096 + pos] = tf32b(src[j]);
    } else if (i < 81920) {                        // Q_P / ff1 [64,64]
        int j = i - 73728;
        const float* src = (j < 4096) ? Q_P : F1;
        uint32_t* dst = (j < 4096) ? g_wQf : g_wF1f;
        int jj = j & 4095;
        int k = jj >> 6, n = jj & 63;
        int pos = ((k >> 3) * 8 + (n >> 3)) * 64 + (((n & 7) << 2) | (k & 3)) * 2 + ((k & 7) >> 2);
        dst[pos] = tf32b(src[jj]);
    } else if (i < 155648) {                       // ff2 [9][64][128]
        int j = i - 81920;
        int t = j >> 13, k = (j >> 7) & 63, n = j & 127;
        int pos = ((k >> 3) * 16 + (n >> 3)) * 64 + (((n & 7) << 2) | (k & 3)) * 2 + ((k & 7) >> 2);
        g_wc2f[t * 8192 + pos] = tf32b(W2[j]);
    } else {                                       // ff3 [9][128][64]
        int j = i - 155648;
        int t = j >> 13, k = (j >> 6) & 127, n = j & 63;
        int ch = k >> 6, kl = k & 63;
        int pos = ((kl >> 3) * 8 + (n >> 3)) * 64 + (((n & 7) << 2) | (kl & 3)) * 2 + ((kl & 7) >> 2);
        g_wc3f[(t * 2 + ch) * 4096 + pos] = tf32b(W3[j]);
    }
}

// ---------------------------------------------------------------------------
// Fully fused: K/V/Q projections + tap attention + softmax + ff1.
// One block = 8x16 pixel tile. 256 threads (8 warps, m-frag 16 px each).
// x-halo (10x18x64, tf32) in smem; per tap: shifted-tile GEMM vs weight chunk.
// Scores from K-MMA accumulators dotted with Q-MMA accumulators (same layout)
// + shfl reduce over the lc-group. Zero-padded halo => OOB taps score 0 and
// contribute 0 to V, matching the reference's masked-multiply softmax.
// Weight stream: 20 stages (Q, K0-8, V0-8, ff1) through 2x16KB double buffer.
// ---------------------------------------------------------------------------
__global__ __launch_bounds__(256) void attn_fused(
    const float* __restrict__ x,
    const uint32_t* __restrict__ wQ, const uint32_t* __restrict__ wK,
    const uint32_t* __restrict__ wV, const uint32_t* __restrict__ wF1,
    const float* __restrict__ bias1, float* __restrict__ t1)
{
    constexpr int HW2 = 18, PST = 68;
    extern __shared__ char smraw[];
    float*    halo = (float*)smraw;                        // 180*68 floats
    uint32_t* Bf   = (uint32_t*)(smraw + 180 * PST * 4);   // 2 x 4096 uints

    const int x0 = blockIdx.x * 16;
    const int y0 = blockIdx.y * 8;
    const int b  = blockIdx.z;
    const int tid = threadIdx.x;
    const int warp = tid >> 5, lane = tid & 31;
    const int lr = lane >> 2, lc = lane & 3;

    // stage 0: Q weights into buf0
    #pragma unroll
    for (int i = 0; i < 4; i++) { int o = (tid + i * 256) * 4; cp16(Bf + o, wQ + o); }
    cp_commit();

    // x-halo: tf32-rounded, zero-padded
    for (int idx = tid * 4; idx < 180 * 64; idx += 1024) {
        int c = idx & 63;
        int sp = idx >> 6;
        int hy = sp / HW2, hx = sp - hy * HW2;
        int gy = y0 + hy - 1, gx = x0 + hx - 1;
        float4 v = make_float4(0.f, 0.f, 0.f, 0.f);
        if ((unsigned)gy < HH && (unsigned)gx < WW)
            v = *(const float4*)(x + (((size_t)b * HH + gy) * WW + gx) * 64 + c);
        float* d = halo + sp * PST + c;
        d[0] = tf32r(v.x); d[1] = tf32r(v.y); d[2] = tf32r(v.z); d[3] = tf32r(v.w);
    }
    cp_wait0();
    __syncthreads();

    // pixel rows of this thread: m = warp*16 + lr (+8); tile coords (warp, lr/lr+8)
    const int off0 = (warp * HW2 + lr) * PST;
    const int off8 = (warp * HW2 + lr + 8) * PST;

    float q[8][4];
    float sc[NP][4];     // [tap][v], v = rowbit*2 + head

    // ---- stage 0: Q GEMM (center offset (1,1)) ----
    {
        // prefetch stage 1 = K0 -> buf1
        #pragma unroll
        for (int i = 0; i < 4; i++) { int o = (tid + i * 256) * 4; cp16(Bf + 4096 + o, wK + o); }
        cp_commit();

        const int toff = (1 * HW2 + 1) * PST;
        float acc[8][4] = {};
        gemm64(acc, Bf + lane * 2, halo + off0 + toff + lc, halo + off8 + toff + lc);
        #pragma unroll
        for (int nf = 0; nf < 8; nf++)
            #pragma unroll
            for (int j = 0; j < 4; j++) q[nf][j] = acc[nf][j];
        cp_wait0();
        __syncthreads();
    }

    // ---- K taps: stages 1..9, buf (t+1)&1 ----
    #pragma unroll
    for (int t = 0; t < NP; t++) {
        {   // prefetch stage t+2 (K(t+1) or V0) -> buf t&1 (last read at stage t, barrier-protected)
            const uint32_t* nsrc = (t < 8) ? wK + (t + 1) * 4096 : wV;
            uint32_t* nb = Bf + (t & 1) * 4096;
            #pragma unroll
            for (int i = 0; i < 4; i++) { int o = (tid + i * 256) * 4; cp16(nb + o, nsrc + o); }
            cp_commit();
        }
        const uint32_t* Bl = Bf + ((t + 1) & 1) * 4096 + lane * 2;
        const int toff = ((t / 3) * HW2 + (t % 3)) * PST;
        float acc[8][4] = {};
        gemm64(acc, Bl, halo + off0 + toff + lc, halo + off8 + toff + lc);

        float p[4] = {0.f, 0.f, 0.f, 0.f};
        #pragma unroll
        for (int nf = 0; nf < 8; nf++) {
            const int hd = nf >> 2;
            p[hd]     += acc[nf][0] * q[nf][0] + acc[nf][1] * q[nf][1];
            p[2 + hd] += acc[nf][2] * q[nf][2] + acc[nf][3] * q[nf][3];
        }
        #pragma unroll
        for (int v = 0; v < 4; v++) {
            p[v] += __shfl_xor_sync(0xffffffffu, p[v], 1);
            p[v] += __shfl_xor_sync(0xffffffffu, p[v], 2);
            sc[t][v] = p[v] * (1.0f / 3.0f);
        }
        cp_wait0();
        __syncthreads();
    }

    // ---- softmax over taps (per pixel-row, per head; duplicated in lc lanes) ----
    #pragma unroll
    for (int v = 0; v < 4; v++) {
        float m = sc[0][v];
        #pragma unroll
        for (int t = 1; t < NP; t++) m = fmaxf(m, sc[t][v]);
        float sum = 0.f;
        #pragma unroll
        for (int t = 0; t < NP; t++) { float e = __expf(sc[t][v] - m); sc[t][v] = e; sum += e; }
        const float inv = 1.0f / sum;
        #pragma unroll
        for (int t = 0; t < NP; t++) sc[t][v] *= inv;
    }

    // ---- V taps: stages 10..18, buf t&1; alpha-weighted accumulate ----
    float attn[8][4] = {};
    #pragma unroll
    for (int t = 0; t < NP; t++) {
        {   // prefetch stage t+11 (V(t+1) or ff1) -> buf (t+1)&1
            const uint32_t* nsrc = (t < 8) ? wV + (t + 1) * 4096 : wF1;
            uint32_t* nb = Bf + ((t + 1) & 1) * 4096;
            #pragma unroll
            for (int i = 0; i < 4; i++) { int o = (tid + i * 256) * 4; cp16(nb + o, nsrc + o); }
            cp_commit();
        }
        const uint32_t* Bl = Bf + (t & 1) * 4096 + lane * 2;
        const int toff = ((t / 3) * HW2 + (t % 3)) * PST;
        float acc[8][4] = {};
        gemm64(acc, Bl, halo + off0 + toff + lc, halo + off8 + toff + lc);

        #pragma unroll
        for (int nf = 0; nf < 8; nf++) {
            const int hd = nf >> 2;
            attn[nf][0] += sc[t][hd]     * acc[nf][0];
            attn[nf][1] += sc[t][hd]     * acc[nf][1];
            attn[nf][2] += sc[t][2 + hd] * acc[nf][2];
            attn[nf][3] += sc[t][2 + hd] * acc[nf][3];
        }
        cp_wait0();
        __syncthreads();
    }

    // ---- ff1: stage 19 (buf1). attn -> smem (tf32) -> GEMM -> t1 ----
    float* Ast = halo;   // halo no longer needed
    #pragma unroll
    for (int nf = 0; nf < 8; nf++) {
        int col = nf * 8 + lc * 2;
        *(float2*)&Ast[(warp * 16 + lr) * PST + col] =
            make_float2(tf32r(attn[nf][0]), tf32r(attn[nf][1]));
        *(float2*)&Ast[(warp * 16 + lr + 8) * PST + col] =
            make_float2(tf32r(attn[nf][2]), tf32r(attn[nf][3]));
    }
    __syncthreads();

    float acc[8][4] = {};
    gemm64(acc, Bf + 4096 + lane * 2,
           Ast + (warp * 16 + lr) * PST + lc,
           Ast + (warp * 16 + lr + 8) * PST + lc);

    const int ygl = y0 + warp;
    const size_t p0 = ((size_t)b * HH + ygl) * WW + x0 + lr;
    const size_t p1 = p0 + 8;
    #pragma unroll
    for (int nf = 0; nf < 8; nf++) {
        int col = nf * 8 + lc * 2;
        float b0 = bias1[col], b1 = bias1[col + 1];
        *(float2*)(t1 + p0 * 64 + col) = make_float2(
            tf32r(fmaxf(acc[nf][0] + b0, 0.f)), tf32r(fmaxf(acc[nf][1] + b1, 0.f)));
        *(float2*)(t1 + p1 * 64 + col) = make_float2(
            tf32r(fmaxf(acc[nf][2] + b0, 0.f)), tf32r(fmaxf(acc[nf][3] + b1, 0.f)));
    }
}

// ---------------------------------------------------------------------------
// 3x3 conv, implicit GEMM. TH=8 x TW=16 tile, 128 threads (4 warps).
// Full-tap double-buffered weight staging (9 stages per chunk).
// conv2: NWN=2, MFS=4.  conv3: NWN=1, MFS=2.
// grid = (W/16, H/8, B)
// ---------------------------------------------------------------------------
template <int CIN, int COUT, int MFS, bool ROUND>
__global__ __launch_bounds__(128, 2) void conv_tf32(
    const float* __restrict__ in, const uint32_t* __restrict__ wfrag,
    const float* __restrict__ bias, float* __restrict__ out)
{
    constexpr int HW2 = 18, PST = 68;
    constexpr int HALO_F = 10 * HW2 * PST;
    constexpr int NWN = COUT / 64;
    constexpr int CHUNKS = CIN / 64;
    constexpr int WTAP = 64 * COUT;            // uints per tap-chunk
    constexpr int CPT = WTAP / 4 / 128;        // cp16 per thread per tap

    extern __shared__ char smraw[];
    float*    halo = (float*)smraw;
    uint32_t* Bf   = (uint32_t*)(smraw + HALO_F * 4);   // 2 x WTAP

    const int x0 = blockIdx.x * 16;
    const int y0 = blockIdx.y * 8;
    const int b  = blockIdx.z;
    const int tid = threadIdx.x;
    const int warp = tid >> 5, lane = tid & 31;
    const int wm = warp / NWN, wn = warp % NWN;
    const int lr = lane >> 2, lc = lane & 3;

    float acc[MFS][8][4] = {};

    int pixoff[MFS][2];
    #pragma unroll
    for (int mf = 0; mf < MFS; mf++)
        #pragma unroll
        for (int r8 = 0; r8 < 2; r8++) {
            int m = wm * (MFS * 16) + mf * 16 + r8 * 8 + lr;
            int py = m >> 4, px = m & 15;
            pixoff[mf][r8] = (py * HW2 + px) * PST;
        }

    for (int ch = 0; ch < CHUNKS; ch++) {
        const int cin0 = ch * 64;
        __syncthreads();   // prior chunk fully consumed (halo + buf0)

        // prime tap 0 (overlaps halo staging)
        {
            const uint32_t* src = wfrag + (size_t)(0 * CHUNKS + ch) * WTAP;
            #pragma unroll
            for (int i = 0; i < CPT; i++) { int o = (tid + i * 128) * 4; cp16(Bf + o, src + o); }
            cp_commit();
        }

        for (int idx = tid * 4; idx < 10 * HW2 * 64; idx += 128 * 4) {
            int c = idx & 63;
            int sp = idx >> 6;
            int hy = sp / HW2, hx = sp - hy * HW2;
            int gy = y0 + hy - 1, gx = x0 + hx - 1;
            float4 v = make_float4(0.f, 0.f, 0.f, 0.f);
            if ((unsigned)gy < HH && (unsigned)gx < WW)
                v = *(const float4*)(in + (((size_t)b * HH + gy) * WW + gx) * CIN + cin0 + c);
            *(float4*)(halo + sp * PST + c) = v;
        }
        cp_wait0();
        __syncthreads();

        for (int t = 0; t < 9; t++) {
            if (t < 8) {
                uint32_t* nb = Bf + ((t + 1) & 1) * WTAP;
                const uint32_t* src = wfrag + (size_t)((t + 1) * CHUNKS + ch) * WTAP;
                #pragma unroll
                for (int i = 0; i < CPT; i++) { int o = (tid + i * 128) * 4; cp16(nb + o, src + o); }
                cp_commit();
            }

            const uint32_t* Bc = Bf + (t & 1) * WTAP;
            const int toff = ((t / 3) * HW2 + (t % 3)) * PST;

            #pragma unroll
            for (int ks = 0; ks < 8; ks++) {
                uint32_t a[MFS][4];
                #pragma unroll
                for (int mf = 0; mf < MFS; mf++) {
                    const float* b0 = halo + pixoff[mf][0] + toff + ks * 8 + lc;
                    const float* b1 = halo + pixoff[mf][1] + toff + ks * 8 + lc;
                    a[mf][0] = __float_as_uint(b0[0]);
                    a[mf][1] = __float_as_uint(b1[0]);
                    a[mf][2] = __float_as_uint(b0[4]);
                    a[mf][3] = __float_as_uint(b1[4]);
                }
                #pragma unroll
                for (int nf = 0; nf < 8; nf++) {
                    int sec = ks * (COUT / 8) + wn * 8 + nf;
                    uint2 bv = *(const uint2*)&Bc[sec * 64 + lane * 2];
                    uint32_t br[2] = {bv.x, bv.y};
                    #pragma unroll
                    for (int mf = 0; mf < MFS; mf++)
                        mma8(acc[mf][nf], a[mf], br);
                }
            }

            if (t < 8) { cp_wait0(); __syncthreads(); }
        }
    }

    #pragma unroll
    for (int mf = 0; mf < MFS; mf++) {
        #pragma unroll
        for (int r8 = 0; r8 < 2; r8++) {
            int m = wm * (MFS * 16) + mf * 16 + r8 * 8 + lr;
            int py = m >> 4, px = m & 15;
            int y = y0 + py, xx = x0 + px;
            size_t base = (((size_t)b * HH + y) * WW + xx) * COUT;
            #pragma unroll
            for (int nf = 0; nf < 8; nf++) {
                int n = wn * 64 + nf * 8 + lc * 2;
                float vx = fmaxf(acc[mf][nf][r8 * 2 + 0] + bias[n], 0.f);
                float vy = fmaxf(acc[mf][nf][r8 * 2 + 1] + bias[n + 1], 0.f);
                if (ROUND) { vx = tf32r(vx); vy = tf32r(vy); }
                *(float2*)(out + base + n) = make_float2(vx, vy);
            }
        }
    }
}

// ---------------------------------------------------------------------------
// Launch
// ---------------------------------------------------------------------------
extern "C" void kernel_launch(void* const* d_in, const int* in_sizes, int n_in,
                              void* d_out, int out_size)
{
    const float* x      = (const float*)d_in[0];
    const float* K_P    = (const float*)d_in[1];
    const float* V_P    = (const float*)d_in[2];
    const float* Q_P    = (const float*)d_in[3];
    const float* ff1_k  = (const float*)d_in[4];
    const float* ff1_b  = (const float*)d_in[5];
    const float* ff2_k  = (const float*)d_in[6];
    const float* ff2_b  = (const float*)d_in[7];
    const float* ff3_k  = (const float*)d_in[8];
    const float* ff3_b  = (const float*)d_in[9];
    float* out = (float*)d_out;

    float *t1, *t2;
    uint32_t *wKf, *wVf, *wQf, *wF1f, *wc2f, *wc3f;
    cudaGetSymbolAddress((void**)&t1,   g_t1);
    cudaGetSymbolAddress((void**)&t2,   g_t2);
    cudaGetSymbolAddress((void**)&wKf,  g_wKf);
    cudaGetSymbolAddress((void**)&wVf,  g_wVf);
    cudaGetSymbolAddress((void**)&wQf,  g_wQf);
    cudaGetSymbolAddress((void**)&wF1f, g_wF1f);
    cudaGetSymbolAddress((void**)&wc2f, g_wc2f);
    cudaGetSymbolAddress((void**)&wc3f, g_wc3f);

    const int FUSED_SMEM = 180 * 68 * 4 + 2 * 4096 * 4;   // 81728
    const int CONV2_SMEM = 180 * 68 * 4 + 2 * 8192 * 4;   // 114496
    const int CONV3_SMEM = 180 * 68 * 4 + 2 * 4096 * 4;   // 81728

    cudaFuncSetAttribute(attn_fused, cudaFuncAttributeMaxDynamicSharedMemorySize, FUSED_SMEM);
    cudaFuncSetAttribute((conv_tf32<64, 128, 4, true>),  cudaFuncAttributeMaxDynamicSharedMemorySize, CONV2_SMEM);
    cudaFuncSetAttribute((conv_tf32<128, 64, 2, false>), cudaFuncAttributeMaxDynamicSharedMemorySize, CONV3_SMEM);

    prep_w<<<896, 256>>>(K_P, V_P, Q_P, ff1_k, ff2_k, ff3_k);

    // Fused projections + attention + ff1
    attn_fused<<<dim3(WW / 16, HH / 8, BB), 256, FUSED_SMEM>>>(
        x, wQf, wKf, wVf, wF1f, ff1_b, t1);

    // Convs
    conv_tf32<64, 128, 4, true><<<dim3(WW / 16, HH / 8, BB), 128, CONV2_SMEM>>>(t1, wc2f, ff2_b, t2);
    conv_tf32<128, 64, 2, false><<<dim3(WW / 16, HH / 8, BB), 128, CONV3_SMEM>>>(t2, wc3f, ff3_b, out);
}